// round 1
// baseline (speedup 1.0000x reference)
#include <cuda_runtime.h>
#include <math.h>

// ---------------- problem constants ----------------
#define B_WIN   2048
#define NTOK    49
#define DIM     384
#define NH      12
#define HD      32
#define NWMASK  64
#define TBL     169            // (2*7-1)^2
#define CPBH    512
#define QKV_N   1152
#define MROWS   (B_WIN * NTOK) // 100352

// ---------------- scratch (device globals; no allocs allowed) ----------------
__device__ float g_qkv[(size_t)MROWS * QKV_N];      // [100352, 1152]
__device__ float g_attout[(size_t)MROWS * DIM];     // [100352, 384]
__device__ float g_bias_table[TBL * NH];            // [169, 12]
__device__ float g_qkv_bias[QKV_N];

// ---------------- prep: build fused qkv bias ----------------
__global__ void build_qkv_bias(const float* __restrict__ q_bias,
                               const float* __restrict__ v_bias) {
    int n = blockIdx.x * blockDim.x + threadIdx.x;
    if (n >= QKV_N) return;
    float b;
    if (n < DIM)            b = q_bias[n];
    else if (n < 2 * DIM)   b = 0.0f;
    else                    b = v_bias[n - 2 * DIM];
    g_qkv_bias[n] = b;
}

// ---------------- prep: CPB MLP -> bias_table[169,12] ----------------
__global__ void cpb_table_kernel(const float* __restrict__ table,   // [169,2]
                                 const float* __restrict__ w1,      // [512,2]
                                 const float* __restrict__ b1,      // [512]
                                 const float* __restrict__ w2) {    // [12,512]
    int id = blockIdx.x * blockDim.x + threadIdx.x;
    if (id >= TBL * NH) return;
    int t = id / NH;
    int h = id % NH;
    float c0 = table[t * 2 + 0];
    float c1 = table[t * 2 + 1];
    const float* w2h = w2 + h * CPBH;
    float acc = 0.0f;
    for (int j = 0; j < CPBH; j++) {
        float hid = fmaxf(c0 * w1[j * 2 + 0] + c1 * w1[j * 2 + 1] + b1[j], 0.0f);
        acc += hid * w2h[j];
    }
    g_bias_table[t * NH + h] = 16.0f / (1.0f + expf(-acc));
}

// ---------------- fp32 SGEMM: C[M,N] = A[M,K] @ W[N,K]^T + bias[N] ----------------
// BM=BN=128, BK=8, 256 threads, 8x8 microtile. M%128==0, N%128==0, K%8==0 assumed.
#define BM 128
#define BN 128
#define BK 8

__global__ void __launch_bounds__(256, 2)
sgemm_bias(const float* __restrict__ A, const float* __restrict__ W,
           const float* __restrict__ bias, float* __restrict__ C,
           int M, int N, int K) {
    __shared__ float As[BK][BM];
    __shared__ float Ws[BK][BN];
    const int tid = threadIdx.x;
    const int bm = blockIdx.y * BM;
    const int bn = blockIdx.x * BN;
    const int tx = tid & 15;       // 0..15 -> n tile
    const int ty = tid >> 4;       // 0..15 -> m tile
    const int lrow = tid >> 1;     // 0..127
    const int lcol = (tid & 1) * 4;

    float acc[8][8];
#pragma unroll
    for (int i = 0; i < 8; i++)
#pragma unroll
        for (int j = 0; j < 8; j++) acc[i][j] = 0.0f;

    const float* Aptr = A + (size_t)(bm + lrow) * K + lcol;
    const float* Wptr = W + (size_t)(bn + lrow) * K + lcol;

    for (int k0 = 0; k0 < K; k0 += BK) {
        float4 a4 = *(const float4*)(Aptr + k0);
        float4 w4 = *(const float4*)(Wptr + k0);
        As[lcol + 0][lrow] = a4.x; As[lcol + 1][lrow] = a4.y;
        As[lcol + 2][lrow] = a4.z; As[lcol + 3][lrow] = a4.w;
        Ws[lcol + 0][lrow] = w4.x; Ws[lcol + 1][lrow] = w4.y;
        Ws[lcol + 2][lrow] = w4.z; Ws[lcol + 3][lrow] = w4.w;
        __syncthreads();
#pragma unroll
        for (int k = 0; k < BK; k++) {
            float ra[8], rb[8];
            float4 t0 = *(const float4*)&As[k][ty * 8];
            float4 t1 = *(const float4*)&As[k][ty * 8 + 4];
            ra[0]=t0.x; ra[1]=t0.y; ra[2]=t0.z; ra[3]=t0.w;
            ra[4]=t1.x; ra[5]=t1.y; ra[6]=t1.z; ra[7]=t1.w;
            float4 u0 = *(const float4*)&Ws[k][tx * 8];
            float4 u1 = *(const float4*)&Ws[k][tx * 8 + 4];
            rb[0]=u0.x; rb[1]=u0.y; rb[2]=u0.z; rb[3]=u0.w;
            rb[4]=u1.x; rb[5]=u1.y; rb[6]=u1.z; rb[7]=u1.w;
#pragma unroll
            for (int i = 0; i < 8; i++)
#pragma unroll
                for (int j = 0; j < 8; j++)
                    acc[i][j] = fmaf(ra[i], rb[j], acc[i][j]);
        }
        __syncthreads();
    }

    // epilogue: add bias, float4 stores
#pragma unroll
    for (int i = 0; i < 8; i++) {
        int m = bm + ty * 8 + i;
        float* Crow = C + (size_t)m * N + bn + tx * 8;
        const float* brow = bias + bn + tx * 8;
#pragma unroll
        for (int j4 = 0; j4 < 2; j4++) {
            float4 o;
            o.x = acc[i][j4 * 4 + 0] + brow[j4 * 4 + 0];
            o.y = acc[i][j4 * 4 + 1] + brow[j4 * 4 + 1];
            o.z = acc[i][j4 * 4 + 2] + brow[j4 * 4 + 2];
            o.w = acc[i][j4 * 4 + 3] + brow[j4 * 4 + 3];
            *(float4*)(Crow + j4 * 4) = o;
        }
    }
}

// ---------------- attention: one block per (window, head) ----------------
#define QPAD 36

__global__ void __launch_bounds__(128)
attn_kernel(const float* __restrict__ mask,        // [64,49,49]
            const float* __restrict__ logit_scale, // [12]
            const int*   __restrict__ rel_idx) {   // [49*49]
    const int bh = blockIdx.x;
    const int b = bh / NH;
    const int h = bh - b * NH;
    const int tid = threadIdx.x;

    __shared__ float qs[NTOK * QPAD];
    __shared__ float ks[NTOK * QPAD];
    __shared__ float vs[NTOK * QPAD];
    __shared__ float fq[NTOK], fk[NTOK];
    __shared__ float att[NTOK * NTOK];

    const float* base = g_qkv + (size_t)b * NTOK * QKV_N + h * HD;
    for (int i = tid; i < NTOK * HD; i += 128) {
        int r = i >> 5, d = i & 31;
        qs[r * QPAD + d] = base[r * QKV_N + d];
        ks[r * QPAD + d] = base[r * QKV_N + DIM + d];
        vs[r * QPAD + d] = base[r * QKV_N + 2 * DIM + d];
    }
    __syncthreads();

    if (tid < NTOK) {
        float sq = 0.0f, sk = 0.0f;
#pragma unroll
        for (int d = 0; d < HD; d++) {
            float a = qs[tid * QPAD + d]; sq += a * a;
            float c = ks[tid * QPAD + d]; sk += c * c;
        }
        float scale = expf(fminf(logit_scale[h], 4.605170185988091f)); // log(100)
        fq[tid] = scale / fmaxf(sqrtf(sq), 1e-12f);
        fk[tid] = 1.0f / fmaxf(sqrtf(sk), 1e-12f);
    }
    __syncthreads();

    for (int i = tid; i < NTOK * HD; i += 128) {
        int r = i >> 5, d = i & 31;
        qs[r * QPAD + d] *= fq[r];
        ks[r * QPAD + d] *= fk[r];
    }
    __syncthreads();

    const float* mrow = mask + (size_t)(b & (NWMASK - 1)) * NTOK * NTOK;
    for (int e = tid; e < NTOK * NTOK; e += 128) {
        int i = e / NTOK, j = e - i * NTOK;
        const float* qr = qs + i * QPAD;
        const float* kr = ks + j * QPAD;
        float s = 0.0f;
#pragma unroll
        for (int d = 0; d < HD; d += 4) {
            float4 a = *(const float4*)(qr + d);
            float4 c = *(const float4*)(kr + d);
            s = fmaf(a.x, c.x, s); s = fmaf(a.y, c.y, s);
            s = fmaf(a.z, c.z, s); s = fmaf(a.w, c.w, s);
        }
        s += g_bias_table[rel_idx[e] * NH + h] + mrow[e];
        att[e] = s;
    }
    __syncthreads();

    if (tid < NTOK) {
        float* row = att + tid * NTOK;
        float m = -1e30f;
#pragma unroll 7
        for (int j = 0; j < NTOK; j++) m = fmaxf(m, row[j]);
        float sum = 0.0f;
#pragma unroll 7
        for (int j = 0; j < NTOK; j++) { float e = expf(row[j] - m); row[j] = e; sum += e; }
        float inv = 1.0f / sum;
#pragma unroll 7
        for (int j = 0; j < NTOK; j++) row[j] *= inv;
    }
    __syncthreads();

    float* ob = g_attout + (size_t)b * NTOK * DIM + h * HD;
    for (int o = tid; o < NTOK * (HD / 4); o += 128) {
        int i = o >> 3;
        int dq = (o & 7) * 4;
        const float* ar = att + i * NTOK;
        float4 acc = make_float4(0.f, 0.f, 0.f, 0.f);
#pragma unroll 7
        for (int j = 0; j < NTOK; j++) {
            float a = ar[j];
            float4 v4 = *(const float4*)(vs + j * QPAD + dq);
            acc.x = fmaf(a, v4.x, acc.x);
            acc.y = fmaf(a, v4.y, acc.y);
            acc.z = fmaf(a, v4.z, acc.z);
            acc.w = fmaf(a, v4.w, acc.w);
        }
        *(float4*)(ob + i * DIM + dq) = acc;
    }
}

// ---------------- launch ----------------
extern "C" void kernel_launch(void* const* d_in, const int* in_sizes, int n_in,
                              void* d_out, int out_size) {
    const float* x           = (const float*)d_in[0];   // [2048,49,384]
    const float* mask        = (const float*)d_in[1];   // [64,49,49]
    const float* qkv_w       = (const float*)d_in[2];   // [1152,384]
    const float* q_bias      = (const float*)d_in[3];   // [384]
    const float* v_bias      = (const float*)d_in[4];   // [384]
    const float* logit_scale = (const float*)d_in[5];   // [12]
    const float* cpb_w1      = (const float*)d_in[6];   // [512,2]
    const float* cpb_b1      = (const float*)d_in[7];   // [512]
    const float* cpb_w2      = (const float*)d_in[8];   // [12,512]
    const float* proj_w      = (const float*)d_in[9];   // [384,384]
    const float* proj_b      = (const float*)d_in[10];  // [384]
    const float* rel_table   = (const float*)d_in[11];  // [169,2]
    const int*   rel_idx     = (const int*)d_in[12];    // [49,49]
    float* out = (float*)d_out;

    // scratch pointers (device globals)
    float* qkv_scratch;  cudaGetSymbolAddress((void**)&qkv_scratch, g_qkv);
    float* att_scratch;  cudaGetSymbolAddress((void**)&att_scratch, g_attout);
    float* qkv_bias_ptr; cudaGetSymbolAddress((void**)&qkv_bias_ptr, g_qkv_bias);

    // prep
    build_qkv_bias<<<(QKV_N + 255) / 256, 256>>>(q_bias, v_bias);
    cpb_table_kernel<<<(TBL * NH + 255) / 256, 256>>>(rel_table, cpb_w1, cpb_b1, cpb_w2);

    // QKV GEMM: [100352,1152] = x[100352,384] @ qkv_w^T + qkv_bias
    {
        dim3 grid(QKV_N / BN, MROWS / BM);
        sgemm_bias<<<grid, 256>>>(x, qkv_w, qkv_bias_ptr, qkv_scratch,
                                  MROWS, QKV_N, DIM);
    }

    // attention per (window, head)
    attn_kernel<<<B_WIN * NH, 128>>>(mask, logit_scale, rel_idx);

    // proj GEMM: out[100352,384] = attout @ proj_w^T + proj_b
    {
        dim3 grid(DIM / BN, MROWS / BM);
        sgemm_bias<<<grid, 256>>>(att_scratch, proj_w, proj_b, out,
                                  MROWS, DIM, DIM);
    }
}

// round 2
// speedup vs baseline: 2.0734x; 2.0734x over previous
#include <cuda_runtime.h>
#include <math.h>

// ---------------- problem constants ----------------
#define B_WIN   2048
#define NTOK    49
#define DIM     384
#define NH      12
#define HD      32
#define NWMASK  64
#define TBL     169
#define CPBH    512
#define QKV_N   1152
#define MROWS   (B_WIN * NTOK)    // 100352
#define NN      (NTOK * NTOK)     // 2401

// ---------------- scratch (device globals) ----------------
__device__ float g_qkv[(size_t)MROWS * QKV_N];
__device__ float g_attout[(size_t)MROWS * DIM];
__device__ float g_bias_table[TBL * NH];
__device__ float g_qkv_bias[QKV_N];
__device__ float g_biasmask[(size_t)NWMASK * NH * NN];   // 7.4 MB fused bias+mask

// ---------------- small helpers ----------------
__device__ __forceinline__ float to_tf32(float x) {
    unsigned u;
    asm("cvt.rna.tf32.f32 %0, %1;" : "=r"(u) : "f"(x));
    return __uint_as_float(u);
}
__device__ __forceinline__ unsigned long long fma2(unsigned long long a,
                                                   unsigned long long b,
                                                   unsigned long long c) {
    unsigned long long d;
    asm("fma.rn.f32x2 %0, %1, %2, %3;" : "=l"(d) : "l"(a), "l"(b), "l"(c));
    return d;
}
__device__ __forceinline__ unsigned long long pack2(float lo, float hi) {
    unsigned long long d;
    asm("mov.b64 %0, {%1, %2};" : "=l"(d) : "f"(lo), "f"(hi));
    return d;
}
__device__ __forceinline__ float2 unpack2(unsigned long long v) {
    float2 r;
    asm("mov.b64 {%0, %1}, %2;" : "=f"(r.x), "=f"(r.y) : "l"(v));
    return r;
}

// ---------------- prep: fused qkv bias ----------------
__global__ void build_qkv_bias(const float* __restrict__ q_bias,
                               const float* __restrict__ v_bias) {
    int n = blockIdx.x * blockDim.x + threadIdx.x;
    if (n >= QKV_N) return;
    float b;
    if (n < DIM)          b = q_bias[n];
    else if (n < 2 * DIM) b = 0.0f;
    else                  b = v_bias[n - 2 * DIM];
    g_qkv_bias[n] = b;
}

// ---------------- prep: CPB MLP -> bias_table[169,12] ----------------
__global__ void cpb_table_kernel(const float* __restrict__ table,
                                 const float* __restrict__ w1,
                                 const float* __restrict__ b1,
                                 const float* __restrict__ w2) {
    int id = blockIdx.x * blockDim.x + threadIdx.x;
    if (id >= TBL * NH) return;
    int t = id / NH;
    int h = id % NH;
    float c0 = table[t * 2 + 0];
    float c1 = table[t * 2 + 1];
    const float* w2h = w2 + h * CPBH;
    float acc = 0.0f;
    for (int j = 0; j < CPBH; j++) {
        float hid = fmaxf(c0 * w1[j * 2 + 0] + c1 * w1[j * 2 + 1] + b1[j], 0.0f);
        acc += hid * w2h[j];
    }
    g_bias_table[t * NH + h] = 16.0f / (1.0f + expf(-acc));
}

// ---------------- prep: fused bias+mask table [64,12,49,49] ----------------
__global__ void biasmask_kernel(const float* __restrict__ mask,
                                const int* __restrict__ rel_idx) {
    int e = blockIdx.x * 256 + threadIdx.x;
    if (e >= NWMASK * NH * NN) return;
    int wh = e / NN;
    int ij = e - wh * NN;
    int w = wh / NH;
    int h = wh - w * NH;
    g_biasmask[e] = g_bias_table[rel_idx[ij] * NH + h] + mask[(size_t)w * NN + ij];
}

// ---------------- tf32 tensor-core GEMM: C = A[M,K] @ W[N,K]^T + bias ----------------
#define GBK  16
#define GLDA 20

__device__ __forceinline__ void mma_tf32(float* c, const unsigned* a, const unsigned* b) {
    asm volatile(
        "mma.sync.aligned.m16n8k8.row.col.f32.tf32.tf32.f32 "
        "{%0,%1,%2,%3}, {%4,%5,%6,%7}, {%8,%9}, {%0,%1,%2,%3};"
        : "+f"(c[0]), "+f"(c[1]), "+f"(c[2]), "+f"(c[3])
        : "r"(a[0]), "r"(a[1]), "r"(a[2]), "r"(a[3]), "r"(b[0]), "r"(b[1]));
}

__device__ __forceinline__ void sts_tile(float* dst, int lr, int lq,
                                         float4 v0, float4 v1) {
    float* p = dst + lr * GLDA + lq;
    float4 t0 = make_float4(to_tf32(v0.x), to_tf32(v0.y), to_tf32(v0.z), to_tf32(v0.w));
    float4 t1 = make_float4(to_tf32(v1.x), to_tf32(v1.y), to_tf32(v1.z), to_tf32(v1.w));
    *(float4*)(p)     = t0;
    *(float4*)(p + 4) = t1;
}

__global__ void __launch_bounds__(256, 2)
gemm_tf32(const float* __restrict__ A, const float* __restrict__ W,
          const float* __restrict__ bias, float* __restrict__ C,
          int M, int N, int K) {
    __shared__ float As[2][128 * GLDA];
    __shared__ float Ws[2][128 * GLDA];
    const int tid  = threadIdx.x;
    const int lane = tid & 31;
    const int warp = tid >> 5;
    const int warpM = (warp >> 2) * 64;
    const int warpN = (warp & 3) * 32;
    const int bm = blockIdx.y * 128;
    const int bn = blockIdx.x * 128;

    const int lr = tid >> 1;
    const int lq = (tid & 1) * 8;
    const float* Ap = A + (size_t)(bm + lr) * K + lq;
    const float* Wp = W + (size_t)(bn + lr) * K + lq;

    float c[4][4][4];
#pragma unroll
    for (int mi = 0; mi < 4; mi++)
#pragma unroll
        for (int ni = 0; ni < 4; ni++)
#pragma unroll
            for (int e = 0; e < 4; e++) c[mi][ni][e] = 0.0f;

    // prime buffer 0
    {
        float4 a0 = *(const float4*)(Ap);
        float4 a1 = *(const float4*)(Ap + 4);
        float4 w0 = *(const float4*)(Wp);
        float4 w1 = *(const float4*)(Wp + 4);
        sts_tile(As[0], lr, lq, a0, a1);
        sts_tile(Ws[0], lr, lq, w0, w1);
    }
    __syncthreads();

    const int nt = K / GBK;
    for (int kt = 0; kt < nt; kt++) {
        const int cur = kt & 1;
        float4 na0, na1, nw0, nw1;
        const bool more = (kt + 1) < nt;
        if (more) {
            const float* pA = Ap + (kt + 1) * GBK;
            const float* pW = Wp + (kt + 1) * GBK;
            na0 = *(const float4*)(pA);
            na1 = *(const float4*)(pA + 4);
            nw0 = *(const float4*)(pW);
            nw1 = *(const float4*)(pW + 4);
        }
        const float* Ab = As[cur];
        const float* Wb = Ws[cur];
        const int r  = lane >> 2;
        const int cc = lane & 3;
#pragma unroll
        for (int ks = 0; ks < 2; ks++) {
            const int k = ks * 8;
            unsigned af[4][4], bf[4][2];
#pragma unroll
            for (int mi = 0; mi < 4; mi++) {
                int rb = warpM + mi * 16 + r;
                af[mi][0] = __float_as_uint(Ab[rb * GLDA + k + cc]);
                af[mi][1] = __float_as_uint(Ab[(rb + 8) * GLDA + k + cc]);
                af[mi][2] = __float_as_uint(Ab[rb * GLDA + k + 4 + cc]);
                af[mi][3] = __float_as_uint(Ab[(rb + 8) * GLDA + k + 4 + cc]);
            }
#pragma unroll
            for (int ni = 0; ni < 4; ni++) {
                int cb = warpN + ni * 8 + r;
                bf[ni][0] = __float_as_uint(Wb[cb * GLDA + k + cc]);
                bf[ni][1] = __float_as_uint(Wb[cb * GLDA + k + 4 + cc]);
            }
#pragma unroll
            for (int mi = 0; mi < 4; mi++)
#pragma unroll
                for (int ni = 0; ni < 4; ni++)
                    mma_tf32(c[mi][ni], af[mi], bf[ni]);
        }
        if (more) {
            sts_tile(As[cur ^ 1], lr, lq, na0, na1);
            sts_tile(Ws[cur ^ 1], lr, lq, nw0, nw1);
        }
        __syncthreads();
    }

    // epilogue: bias + float2 stores
#pragma unroll
    for (int mi = 0; mi < 4; mi++) {
        int r0 = bm + warpM + mi * 16 + (lane >> 2);
#pragma unroll
        for (int ni = 0; ni < 4; ni++) {
            int col = bn + warpN + ni * 8 + (lane & 3) * 2;
            float b0 = bias[col];
            float b1 = bias[col + 1];
            *(float2*)(C + (size_t)r0 * N + col) =
                make_float2(c[mi][ni][0] + b0, c[mi][ni][1] + b1);
            *(float2*)(C + (size_t)(r0 + 8) * N + col) =
                make_float2(c[mi][ni][2] + b0, c[mi][ni][3] + b1);
        }
    }
}

// ---------------- attention: one (window, head) per 64-thread block ----------------
__global__ void __launch_bounds__(64)
attn2(const float* __restrict__ logit_scale) {
    const int bh = blockIdx.x;
    const int b = bh / NH;
    const int h = bh - b * NH;
    const int tid = threadIdx.x;

    __shared__ float ks[NTOK * 36];
    __shared__ float vs[NTOK * 36];
    __shared__ float bmx[NN];
    __shared__ float att[NN];
    __shared__ float fk[NTOK];

    const float* base = g_qkv + (size_t)b * NTOK * QKV_N + h * HD;
    for (int e = tid; e < NTOK * 8; e += 64) {
        int r = e >> 3, q4 = (e & 7) * 4;
        *(float4*)(ks + r * 36 + q4) = *(const float4*)(base + (size_t)r * QKV_N + DIM + q4);
        *(float4*)(vs + r * 36 + q4) = *(const float4*)(base + (size_t)r * QKV_N + 2 * DIM + q4);
    }
    const float* bmg = g_biasmask + (size_t)((b & (NWMASK - 1)) * NH + h) * NN;
    for (int e = tid; e < NN; e += 64) bmx[e] = bmg[e];
    __syncthreads();

    if (tid < NTOK) {
        float s = 0.0f;
#pragma unroll
        for (int d = 0; d < HD; d++) { float k = ks[tid * 36 + d]; s += k * k; }
        fk[tid] = 1.0f / fmaxf(sqrtf(s), 1e-12f);
    }
    __syncthreads();

    const int i = tid;
    if (i < NTOK) {
        // q row: load, scale by exp(min(logit_scale,log100))/||q||, pack f32x2
        float qf[HD];
        const float* qg = base + (size_t)i * QKV_N;
#pragma unroll
        for (int t = 0; t < 8; t++)
            *(float4*)(qf + t * 4) = *(const float4*)(qg + t * 4);
        float sq = 0.0f;
#pragma unroll
        for (int d = 0; d < HD; d++) sq += qf[d] * qf[d];
        float scale = expf(fminf(logit_scale[h], 4.605170185988091f));
        float fs = scale / fmaxf(sqrtf(sq), 1e-12f);
        unsigned long long qp[16];
#pragma unroll
        for (int t = 0; t < 16; t++) qp[t] = pack2(qf[2 * t] * fs, qf[2 * t + 1] * fs);

        float* arow = att + i * NTOK;
        const float* bmrow = bmx + i * NTOK;
        for (int j = 0; j < NTOK; j++) {
            const ulonglong2* kr = (const ulonglong2*)(ks + j * 36);
            unsigned long long acc = 0ull;
#pragma unroll
            for (int t = 0; t < 8; t++) {
                ulonglong2 kk = kr[t];
                acc = fma2(qp[2 * t], kk.x, acc);
                acc = fma2(qp[2 * t + 1], kk.y, acc);
            }
            float2 av = unpack2(acc);
            arow[j] = (av.x + av.y) * fk[j] + bmrow[j];
        }

        // softmax (in smem row, conflict-free stride 49)
        float m = -1e30f;
        for (int j = 0; j < NTOK; j++) m = fmaxf(m, arow[j]);
        float sum = 0.0f;
        for (int j = 0; j < NTOK; j++) {
            float e = expf(arow[j] - m);
            arow[j] = e;
            sum += e;
        }
        float inv = 1.0f / sum;

        // AV with f32x2 accumulators; 1/sum folded into store
        unsigned long long o[16];
#pragma unroll
        for (int t = 0; t < 16; t++) o[t] = 0ull;
        for (int j = 0; j < NTOK; j++) {
            float a = arow[j];
            unsigned long long pa = pack2(a, a);
            const ulonglong2* vr = (const ulonglong2*)(vs + j * 36);
#pragma unroll
            for (int t = 0; t < 8; t++) {
                ulonglong2 vv = vr[t];
                o[2 * t]     = fma2(pa, vv.x, o[2 * t]);
                o[2 * t + 1] = fma2(pa, vv.y, o[2 * t + 1]);
            }
        }
        float* orow = g_attout + ((size_t)b * NTOK + i) * DIM + h * HD;
#pragma unroll
        for (int t = 0; t < 8; t++) {
            float2 lo = unpack2(o[2 * t]);
            float2 hi = unpack2(o[2 * t + 1]);
            *(float4*)(orow + t * 4) =
                make_float4(lo.x * inv, lo.y * inv, hi.x * inv, hi.y * inv);
        }
    }
}

// ---------------- launch ----------------
extern "C" void kernel_launch(void* const* d_in, const int* in_sizes, int n_in,
                              void* d_out, int out_size) {
    const float* x           = (const float*)d_in[0];
    const float* mask        = (const float*)d_in[1];
    const float* qkv_w       = (const float*)d_in[2];
    const float* q_bias      = (const float*)d_in[3];
    const float* v_bias      = (const float*)d_in[4];
    const float* logit_scale = (const float*)d_in[5];
    const float* cpb_w1      = (const float*)d_in[6];
    const float* cpb_b1      = (const float*)d_in[7];
    const float* cpb_w2      = (const float*)d_in[8];
    const float* proj_w      = (const float*)d_in[9];
    const float* proj_b      = (const float*)d_in[10];
    const float* rel_table   = (const float*)d_in[11];
    const int*   rel_idx     = (const int*)d_in[12];
    float* out = (float*)d_out;

    float* qkv_scratch;  cudaGetSymbolAddress((void**)&qkv_scratch, g_qkv);
    float* att_scratch;  cudaGetSymbolAddress((void**)&att_scratch, g_attout);
    float* qkv_bias_ptr; cudaGetSymbolAddress((void**)&qkv_bias_ptr, g_qkv_bias);

    build_qkv_bias<<<(QKV_N + 255) / 256, 256>>>(q_bias, v_bias);
    cpb_table_kernel<<<(TBL * NH + 255) / 256, 256>>>(rel_table, cpb_w1, cpb_b1, cpb_w2);
    biasmask_kernel<<<(NWMASK * NH * NN + 255) / 256, 256>>>(mask, rel_idx);

    // QKV GEMM (tf32 tensor cores): [100352,1152] = x @ qkv_w^T + bias
    {
        dim3 grid(QKV_N / 128, MROWS / 128);
        gemm_tf32<<<grid, 256>>>(x, qkv_w, qkv_bias_ptr, qkv_scratch,
                                 MROWS, QKV_N, DIM);
    }

    attn2<<<B_WIN * NH, 64>>>(logit_scale);

    // proj GEMM: out = attout @ proj_w^T + proj_b
    {
        dim3 grid(DIM / 128, MROWS / 128);
        gemm_tf32<<<grid, 256>>>(att_scratch, proj_w, proj_b, out,
                                 MROWS, DIM, DIM);
    }
}

// round 4
// speedup vs baseline: 2.3253x; 1.1215x over previous
#include <cuda_runtime.h>
#include <math.h>
#include <stdint.h>

// ---------------- problem constants ----------------
#define B_WIN   2048
#define NTOK    49
#define DIM     384
#define NH      12
#define HD      32
#define NWMASK  64
#define TBL     169
#define CPBH    512
#define QKV_N   1152
#define MROWS   (B_WIN * NTOK)    // 100352
#define NN      (NTOK * NTOK)     // 2401
#define KDIM    384

// ---------------- scratch (device globals) ----------------
__device__ float g_qkv[(size_t)MROWS * QKV_N];
__device__ float g_attout[(size_t)MROWS * DIM];
__device__ float g_bias_table[TBL * NH];
__device__ float g_qkv_bias[QKV_N];
__device__ float g_biasmask[(size_t)NWMASK * NH * NN];

// ---------------- helpers ----------------
__device__ __forceinline__ float to_tf32(float x) {
    unsigned u;
    asm("cvt.rna.tf32.f32 %0, %1;" : "=r"(u) : "f"(x));
    return __uint_as_float(u);
}
__device__ __forceinline__ unsigned long long fma2(unsigned long long a,
                                                   unsigned long long b,
                                                   unsigned long long c) {
    unsigned long long d;
    asm("fma.rn.f32x2 %0, %1, %2, %3;" : "=l"(d) : "l"(a), "l"(b), "l"(c));
    return d;
}
__device__ __forceinline__ unsigned long long add2(unsigned long long a,
                                                   unsigned long long b) {
    unsigned long long d;
    asm("add.rn.f32x2 %0, %1, %2;" : "=l"(d) : "l"(a), "l"(b));
    return d;
}
__device__ __forceinline__ unsigned long long pack2(float lo, float hi) {
    unsigned long long d;
    asm("mov.b64 %0, {%1, %2};" : "=l"(d) : "f"(lo), "f"(hi));
    return d;
}
__device__ __forceinline__ float2 unpack2(unsigned long long v) {
    float2 r;
    asm("mov.b64 {%0, %1}, %2;" : "=f"(r.x), "=f"(r.y) : "l"(v));
    return r;
}

// ---------------- prep kernels ----------------
__global__ void build_qkv_bias(const float* __restrict__ q_bias,
                               const float* __restrict__ v_bias) {
    int n = blockIdx.x * blockDim.x + threadIdx.x;
    if (n >= QKV_N) return;
    float b;
    if (n < DIM)          b = q_bias[n];
    else if (n < 2 * DIM) b = 0.0f;
    else                  b = v_bias[n - 2 * DIM];
    g_qkv_bias[n] = b;
}

__global__ void cpb_table_kernel(const float* __restrict__ table,
                                 const float* __restrict__ w1,
                                 const float* __restrict__ b1,
                                 const float* __restrict__ w2) {
    int id = blockIdx.x * blockDim.x + threadIdx.x;
    if (id >= TBL * NH) return;
    int t = id / NH;
    int h = id % NH;
    float c0 = table[t * 2 + 0];
    float c1 = table[t * 2 + 1];
    const float* w2h = w2 + h * CPBH;
    float acc = 0.0f;
    for (int j = 0; j < CPBH; j++) {
        float hid = fmaxf(c0 * w1[j * 2 + 0] + c1 * w1[j * 2 + 1] + b1[j], 0.0f);
        acc += hid * w2h[j];
    }
    g_bias_table[t * NH + h] = 16.0f / (1.0f + expf(-acc));
}

__global__ void biasmask_kernel(const float* __restrict__ mask,
                                const int* __restrict__ rel_idx) {
    int e = blockIdx.x * 256 + threadIdx.x;
    if (e >= NWMASK * NH * NN) return;
    int wh = e / NN;
    int ij = e - wh * NN;
    int w = wh / NH;
    int h = wh - w * NH;
    g_biasmask[e] = g_bias_table[rel_idx[ij] * NH + h] + mask[(size_t)w * NN + ij];
}

// ---------------- tf32 mma.sync GEMM v2 ----------------
// C[M,Ntot] = A[M,384] @ W[Ntot,384]^T + bias
// block tile 256x128, warp tile 64x64 (8 warps: 4 m-bands x 2 n-halves), BK=16.
#define BM2   256
#define BN2   128
#define BK2   16
#define LDA2  20
#define ASZ   (BM2 * LDA2)   // 5120 floats
#define BSZ   (BN2 * LDA2)   // 2560 floats
#define GSMEM ((ASZ + BSZ) * 2 * 4)  // 61440 bytes

__device__ __forceinline__ void mma_tf32(float* c, const unsigned* a,
                                         unsigned b0, unsigned b1) {
    asm volatile(
        "mma.sync.aligned.m16n8k8.row.col.f32.tf32.tf32.f32 "
        "{%0,%1,%2,%3}, {%4,%5,%6,%7}, {%8,%9}, {%0,%1,%2,%3};"
        : "+f"(c[0]), "+f"(c[1]), "+f"(c[2]), "+f"(c[3])
        : "r"(a[0]), "r"(a[1]), "r"(a[2]), "r"(a[3]), "r"(b0), "r"(b1));
}

__global__ void __launch_bounds__(256, 1)
gemm_v2(const float* __restrict__ A, const float* __restrict__ W,
        const float* __restrict__ bias, float* __restrict__ C, int Ntot) {
    extern __shared__ float sm[];
    float* As = sm;                 // [2][ASZ]
    float* Bs = sm + 2 * ASZ;       // [2][BSZ]
    const int tid  = threadIdx.x;
    const int lane = tid & 31;
    const int wid  = tid >> 5;
    const int warpM = (wid >> 1) * 64;
    const int warpN = (wid & 1) * 64;
    const int bm = blockIdx.y * BM2;
    const int bn = blockIdx.x * BN2;

    // staging indices: 4 threads per row (each row = 16 floats = 4 float4)
    const int sar = tid >> 2;        // base row (A: +64*i)
    const int sac = (tid & 3) * 4;   // k offset

    const float* Ag = A + (size_t)(bm + sar) * KDIM + sac;
    const float* Wg = W + (size_t)(bn + sar) * KDIM + sac;

    float c[4][8][4];
#pragma unroll
    for (int mi = 0; mi < 4; mi++)
#pragma unroll
        for (int ni = 0; ni < 8; ni++)
#pragma unroll
            for (int e = 0; e < 4; e++) c[mi][ni][e] = 0.0f;

    float4 astg[4], bstg[2];
    // prologue: chunk 0 -> regs -> smem buf 0
#pragma unroll
    for (int i = 0; i < 4; i++)
        astg[i] = *(const float4*)(Ag + (size_t)(i * 64) * KDIM);
#pragma unroll
    for (int i = 0; i < 2; i++)
        bstg[i] = *(const float4*)(Wg + (size_t)(i * 64) * KDIM);
    {
        float* dst = As;
#pragma unroll
        for (int i = 0; i < 4; i++) {
            float* p = dst + (sar + i * 64) * LDA2 + sac;
            p[0] = to_tf32(astg[i].x); p[1] = to_tf32(astg[i].y);
            p[2] = to_tf32(astg[i].z); p[3] = to_tf32(astg[i].w);
        }
        float* db = Bs;
#pragma unroll
        for (int i = 0; i < 2; i++) {
            float* p = db + (sar + i * 64) * LDA2 + sac;
            p[0] = to_tf32(bstg[i].x); p[1] = to_tf32(bstg[i].y);
            p[2] = to_tf32(bstg[i].z); p[3] = to_tf32(bstg[i].w);
        }
    }
    __syncthreads();

    const int NT = KDIM / BK2;   // 24
    const int r  = lane >> 2;
    const int cc = lane & 3;

    for (int ch = 0; ch < NT; ch++) {
        const int buf = ch & 1;
        const bool more = (ch + 1) < NT;
        if (more) {
            const float* pa = Ag + (ch + 1) * BK2;
            const float* pw = Wg + (ch + 1) * BK2;
#pragma unroll
            for (int i = 0; i < 4; i++)
                astg[i] = *(const float4*)(pa + (size_t)(i * 64) * KDIM);
#pragma unroll
            for (int i = 0; i < 2; i++)
                bstg[i] = *(const float4*)(pw + (size_t)(i * 64) * KDIM);
        }
        const float* Ab = As + buf * ASZ + warpM * LDA2;
        const float* Wb = Bs + buf * BSZ + warpN * LDA2;
#pragma unroll
        for (int ks = 0; ks < 2; ks++) {
            const int k = ks * 8;
            unsigned af[4][4];
#pragma unroll
            for (int mi = 0; mi < 4; mi++) {
                int base = (mi * 16 + r) * LDA2 + k + cc;
                af[mi][0] = __float_as_uint(Ab[base]);
                af[mi][1] = __float_as_uint(Ab[base + 8 * LDA2]);
                af[mi][2] = __float_as_uint(Ab[base + 4]);
                af[mi][3] = __float_as_uint(Ab[base + 8 * LDA2 + 4]);
            }
#pragma unroll
            for (int ni = 0; ni < 8; ni++) {
                int bb = (ni * 8 + r) * LDA2 + k + cc;
                unsigned b0 = __float_as_uint(Wb[bb]);
                unsigned b1 = __float_as_uint(Wb[bb + 4]);
#pragma unroll
                for (int mi = 0; mi < 4; mi++)
                    mma_tf32(c[mi][ni], af[mi], b0, b1);
            }
        }
        if (more) {
            const int nb = buf ^ 1;
            float* dst = As + nb * ASZ;
#pragma unroll
            for (int i = 0; i < 4; i++) {
                float* p = dst + (sar + i * 64) * LDA2 + sac;
                p[0] = to_tf32(astg[i].x); p[1] = to_tf32(astg[i].y);
                p[2] = to_tf32(astg[i].z); p[3] = to_tf32(astg[i].w);
            }
            float* db = Bs + nb * BSZ;
#pragma unroll
            for (int i = 0; i < 2; i++) {
                float* p = db + (sar + i * 64) * LDA2 + sac;
                p[0] = to_tf32(bstg[i].x); p[1] = to_tf32(bstg[i].y);
                p[2] = to_tf32(bstg[i].z); p[3] = to_tf32(bstg[i].w);
            }
            __syncthreads();
        }
    }

    // epilogue: bias + float2 stores
#pragma unroll
    for (int mi = 0; mi < 4; mi++) {
        int row0 = bm + warpM + mi * 16 + r;
#pragma unroll
        for (int ni = 0; ni < 8; ni++) {
            int col = bn + warpN + ni * 8 + cc * 2;
            float2 b2 = *(const float2*)(bias + col);
            *(float2*)(C + (size_t)row0 * Ntot + col) =
                make_float2(c[mi][ni][0] + b2.x, c[mi][ni][1] + b2.y);
            *(float2*)(C + (size_t)(row0 + 8) * Ntot + col) =
                make_float2(c[mi][ni][2] + b2.x, c[mi][ni][3] + b2.y);
        }
    }
}

// ---------------- attention: one (window, head) per 64-thread block ----------------
__global__ void __launch_bounds__(64)
attn2(const float* __restrict__ logit_scale) {
    const int bh = blockIdx.x;
    const int b = bh / NH;
    const int h = bh - b * NH;
    const int tid = threadIdx.x;

    __shared__ float ks[NTOK * 36];
    __shared__ float vs[NTOK * 36];
    __shared__ float bmx[NN];
    __shared__ float att[NN];
    __shared__ float fk[NTOK];

    const float* base = g_qkv + (size_t)b * NTOK * QKV_N + h * HD;
    for (int e = tid; e < NTOK * 8; e += 64) {
        int r = e >> 3, q4 = (e & 7) * 4;
        *(float4*)(ks + r * 36 + q4) = *(const float4*)(base + (size_t)r * QKV_N + DIM + q4);
        *(float4*)(vs + r * 36 + q4) = *(const float4*)(base + (size_t)r * QKV_N + 2 * DIM + q4);
    }
    const float* bmg = g_biasmask + (size_t)((b & (NWMASK - 1)) * NH + h) * NN;
    for (int e = tid; e < NN; e += 64) bmx[e] = bmg[e];
    __syncthreads();

    if (tid < NTOK) {
        float s = 0.0f;
#pragma unroll
        for (int d = 0; d < HD; d++) { float k = ks[tid * 36 + d]; s += k * k; }
        fk[tid] = 1.0f / fmaxf(sqrtf(s), 1e-12f);
    }
    __syncthreads();

    const int i = tid;
    if (i < NTOK) {
        float qf[HD];
        const float* qg = base + (size_t)i * QKV_N;
#pragma unroll
        for (int t = 0; t < 8; t++)
            *(float4*)(qf + t * 4) = *(const float4*)(qg + t * 4);
        float sq = 0.0f;
#pragma unroll
        for (int d = 0; d < HD; d++) sq += qf[d] * qf[d];
        float scale = expf(fminf(logit_scale[h], 4.605170185988091f));
        float fs = scale / fmaxf(sqrtf(sq), 1e-12f);
        unsigned long long qp[16];
#pragma unroll
        for (int t = 0; t < 16; t++) qp[t] = pack2(qf[2 * t] * fs, qf[2 * t + 1] * fs);

        float* arow = att + i * NTOK;
        const float* bmrow = bmx + i * NTOK;
        for (int j = 0; j < NTOK; j++) {
            const ulonglong2* kr = (const ulonglong2*)(ks + j * 36);
            unsigned long long a0 = 0ull, a1 = 0ull, a2 = 0ull, a3 = 0ull;
#pragma unroll
            for (int t = 0; t < 4; t++) {
                ulonglong2 k0 = kr[2 * t];
                ulonglong2 k1 = kr[2 * t + 1];
                a0 = fma2(qp[4 * t + 0], k0.x, a0);
                a1 = fma2(qp[4 * t + 1], k0.y, a1);
                a2 = fma2(qp[4 * t + 2], k1.x, a2);
                a3 = fma2(qp[4 * t + 3], k1.y, a3);
            }
            float2 av = unpack2(add2(add2(a0, a1), add2(a2, a3)));
            arow[j] = (av.x + av.y) * fk[j] + bmrow[j];
        }

        float m = -1e30f;
        for (int j = 0; j < NTOK; j++) m = fmaxf(m, arow[j]);
        float sum = 0.0f;
        for (int j = 0; j < NTOK; j++) {
            float e = expf(arow[j] - m);
            arow[j] = e;
            sum += e;
        }
        float inv = 1.0f / sum;

        unsigned long long o[16];
#pragma unroll
        for (int t = 0; t < 16; t++) o[t] = 0ull;
        for (int j = 0; j < NTOK; j++) {
            float a = arow[j];
            unsigned long long pa = pack2(a, a);
            const ulonglong2* vr = (const ulonglong2*)(vs + j * 36);
#pragma unroll
            for (int t = 0; t < 8; t++) {
                ulonglong2 vv = vr[t];
                o[2 * t]     = fma2(pa, vv.x, o[2 * t]);
                o[2 * t + 1] = fma2(pa, vv.y, o[2 * t + 1]);
            }
        }
        float* orow = g_attout + ((size_t)b * NTOK + i) * DIM + h * HD;
#pragma unroll
        for (int t = 0; t < 8; t++) {
            float2 lo = unpack2(o[2 * t]);
            float2 hi = unpack2(o[2 * t + 1]);
            *(float4*)(orow + t * 4) =
                make_float4(lo.x * inv, lo.y * inv, hi.x * inv, hi.y * inv);
        }
    }
}

// ---------------- launch ----------------
extern "C" void kernel_launch(void* const* d_in, const int* in_sizes, int n_in,
                              void* d_out, int out_size) {
    const float* x           = (const float*)d_in[0];
    const float* mask        = (const float*)d_in[1];
    const float* qkv_w       = (const float*)d_in[2];
    const float* q_bias      = (const float*)d_in[3];
    const float* v_bias      = (const float*)d_in[4];
    const float* logit_scale = (const float*)d_in[5];
    const float* cpb_w1      = (const float*)d_in[6];
    const float* cpb_b1      = (const float*)d_in[7];
    const float* cpb_w2      = (const float*)d_in[8];
    const float* proj_w      = (const float*)d_in[9];
    const float* proj_b      = (const float*)d_in[10];
    const float* rel_table   = (const float*)d_in[11];
    const int*   rel_idx     = (const int*)d_in[12];
    float* out = (float*)d_out;

    float* qkv_scratch;  cudaGetSymbolAddress((void**)&qkv_scratch, g_qkv);
    float* att_scratch;  cudaGetSymbolAddress((void**)&att_scratch, g_attout);
    float* qkv_bias_ptr; cudaGetSymbolAddress((void**)&qkv_bias_ptr, g_qkv_bias);

    cudaFuncSetAttribute(gemm_v2, cudaFuncAttributeMaxDynamicSharedMemorySize, GSMEM);

    build_qkv_bias<<<(QKV_N + 255) / 256, 256>>>(q_bias, v_bias);
    cpb_table_kernel<<<(TBL * NH + 255) / 256, 256>>>(rel_table, cpb_w1, cpb_b1, cpb_w2);
    biasmask_kernel<<<(NWMASK * NH * NN + 255) / 256, 256>>>(mask, rel_idx);

    // QKV GEMM: [100352,1152] = x @ qkv_w^T + bias
    {
        dim3 grid(QKV_N / BN2, MROWS / BM2);
        gemm_v2<<<grid, 256, GSMEM>>>(x, qkv_w, qkv_bias_ptr, qkv_scratch, QKV_N);
    }

    attn2<<<B_WIN * NH, 64>>>(logit_scale);

    // proj GEMM: out = attout @ proj_w^T + proj_b
    {
        dim3 grid(DIM / BN2, MROWS / BM2);
        gemm_v2<<<grid, 256, GSMEM>>>(att_scratch, proj_w, proj_b, out, DIM);
    }
}

// round 5
// speedup vs baseline: 2.3728x; 1.0204x over previous
#include <cuda_runtime.h>
#include <math.h>
#include <stdint.h>

// ---------------- problem constants ----------------
#define B_WIN   2048
#define NTOK    49
#define DIM     384
#define NH      12
#define HD      32
#define NWMASK  64
#define TBL     169
#define CPBH    512
#define QKV_N   1152
#define MROWS   (B_WIN * NTOK)    // 100352
#define NN      (NTOK * NTOK)     // 2401
#define KDIM    384

// ---------------- scratch (device globals) ----------------
__device__ float g_qkv[(size_t)MROWS * QKV_N];
__device__ float g_attout[(size_t)MROWS * DIM];
__device__ float g_bias_table[TBL * NH];
__device__ float g_qkv_bias[QKV_N];
__device__ float g_biasmask[(size_t)NWMASK * NH * NN];

// ---------------- helpers ----------------
__device__ __forceinline__ float to_tf32(float x) {
    unsigned u;
    asm("cvt.rna.tf32.f32 %0, %1;" : "=r"(u) : "f"(x));
    return __uint_as_float(u);
}
__device__ __forceinline__ unsigned long long fma2(unsigned long long a,
                                                   unsigned long long b,
                                                   unsigned long long c) {
    unsigned long long d;
    asm("fma.rn.f32x2 %0, %1, %2, %3;" : "=l"(d) : "l"(a), "l"(b), "l"(c));
    return d;
}
__device__ __forceinline__ unsigned long long add2(unsigned long long a,
                                                   unsigned long long b) {
    unsigned long long d;
    asm("add.rn.f32x2 %0, %1, %2;" : "=l"(d) : "l"(a), "l"(b));
    return d;
}
__device__ __forceinline__ unsigned long long pack2(float lo, float hi) {
    unsigned long long d;
    asm("mov.b64 %0, {%1, %2};" : "=l"(d) : "f"(lo), "f"(hi));
    return d;
}
__device__ __forceinline__ float2 unpack2(unsigned long long v) {
    float2 r;
    asm("mov.b64 {%0, %1}, %2;" : "=f"(r.x), "=f"(r.y) : "l"(v));
    return r;
}

// ---------------- prep kernels ----------------
__global__ void build_qkv_bias(const float* __restrict__ q_bias,
                               const float* __restrict__ v_bias) {
    int n = blockIdx.x * blockDim.x + threadIdx.x;
    if (n >= QKV_N) return;
    float b;
    if (n < DIM)          b = q_bias[n];
    else if (n < 2 * DIM) b = 0.0f;
    else                  b = v_bias[n - 2 * DIM];
    g_qkv_bias[n] = b;
}

__global__ void cpb_table_kernel(const float* __restrict__ table,
                                 const float* __restrict__ w1,
                                 const float* __restrict__ b1,
                                 const float* __restrict__ w2) {
    int id = blockIdx.x * blockDim.x + threadIdx.x;
    if (id >= TBL * NH) return;
    int t = id / NH;
    int h = id % NH;
    float c0 = table[t * 2 + 0];
    float c1 = table[t * 2 + 1];
    const float* w2h = w2 + h * CPBH;
    float acc = 0.0f;
    for (int j = 0; j < CPBH; j++) {
        float hid = fmaxf(c0 * w1[j * 2 + 0] + c1 * w1[j * 2 + 1] + b1[j], 0.0f);
        acc += hid * w2h[j];
    }
    g_bias_table[t * NH + h] = 16.0f / (1.0f + expf(-acc));
}

__global__ void biasmask_kernel(const float* __restrict__ mask,
                                const int* __restrict__ rel_idx) {
    int e = blockIdx.x * 256 + threadIdx.x;
    if (e >= NWMASK * NH * NN) return;
    int wh = e / NN;
    int ij = e - wh * NN;
    int w = wh / NH;
    int h = wh - w * NH;
    g_biasmask[e] = g_bias_table[rel_idx[ij] * NH + h] + mask[(size_t)w * NN + ij];
}

// ---------------- tf32 mma.sync GEMM v3 (permuted smem, LDS.128 frags) ----------
// C[M,Ntot] = A[M,384] @ W[Ntot,384]^T + bias
// block 256x128, warp 64x64 (8 warps: 4 m-bands x 2 n-halves), BK=16, double buf.
// Within each 16-col K-chunk per row, columns are permuted: pos(c) = (c&3)*4 + (c>>2).
// Row stride LDK=20 floats -> conflict-free STS.32 staging and minimal-phase LDS.128.
#define BM3   256
#define BN3   128
#define BK3   16
#define LDK   20
#define A_BUF (BM3 * LDK)   // 5120 floats
#define B_BUF (BN3 * LDK)   // 2560 floats
#define GSMEM ((A_BUF + B_BUF) * 2 * 4)  // 61440 bytes

__device__ __forceinline__ void mma_tf32(float* c, const unsigned* a,
                                         unsigned b0, unsigned b1) {
    asm volatile(
        "mma.sync.aligned.m16n8k8.row.col.f32.tf32.tf32.f32 "
        "{%0,%1,%2,%3}, {%4,%5,%6,%7}, {%8,%9}, {%0,%1,%2,%3};"
        : "+f"(c[0]), "+f"(c[1]), "+f"(c[2]), "+f"(c[3])
        : "r"(a[0]), "r"(a[1]), "r"(a[2]), "r"(a[3]), "r"(b0), "r"(b1));
}

__global__ void __launch_bounds__(256, 1)
gemm_v3(const float* __restrict__ A, const float* __restrict__ W,
        const float* __restrict__ bias, float* __restrict__ C, int Ntot) {
    extern __shared__ float sm[];
    float* As = sm;                 // [2][A_BUF]
    float* Bs = sm + 2 * A_BUF;     // [2][B_BUF]
    const int tid  = threadIdx.x;
    const int lane = tid & 31;
    const int wid  = tid >> 5;
    const int warpM = (wid >> 1) * 64;
    const int warpN = (wid & 1) * 64;
    const int bm = blockIdx.y * BM3;
    const int bn = blockIdx.x * BN3;

    // staging: 4 threads per row, each thread handles 4 consecutive k (one float4)
    const int sar = tid >> 2;        // row 0..63 (A adds +64*i)
    const int s   = tid & 3;         // which 4-col group (sac = s*4)

    const float* Ag = A + (size_t)(bm + sar) * KDIM + s * 4;
    const float* Wg = W + (size_t)(bn + sar) * KDIM + s * 4;

    float c[4][8][4];
#pragma unroll
    for (int mi = 0; mi < 4; mi++)
#pragma unroll
        for (int ni = 0; ni < 8; ni++)
#pragma unroll
            for (int e = 0; e < 4; e++) c[mi][ni][e] = 0.0f;

    float4 astg[4], bstg[2];
    // prologue: load chunk 0 -> permuted smem buf 0
#pragma unroll
    for (int i = 0; i < 4; i++)
        astg[i] = *(const float4*)(Ag + (size_t)(i * 64) * KDIM);
#pragma unroll
    for (int i = 0; i < 2; i++)
        bstg[i] = *(const float4*)(Wg + (size_t)(i * 64) * KDIM);
    {
#pragma unroll
        for (int i = 0; i < 4; i++) {
            float* p = As + (sar + i * 64) * LDK + s;
            p[0]  = to_tf32(astg[i].x); p[4]  = to_tf32(astg[i].y);
            p[8]  = to_tf32(astg[i].z); p[12] = to_tf32(astg[i].w);
        }
#pragma unroll
        for (int i = 0; i < 2; i++) {
            float* p = Bs + (sar + i * 64) * LDK + s;
            p[0]  = to_tf32(bstg[i].x); p[4]  = to_tf32(bstg[i].y);
            p[8]  = to_tf32(bstg[i].z); p[12] = to_tf32(bstg[i].w);
        }
    }
    __syncthreads();

    const int NT = KDIM / BK3;   // 24
    const int r  = lane >> 2;
    const int cc = lane & 3;

    for (int ch = 0; ch < NT; ch++) {
        const int buf = ch & 1;
        const bool more = (ch + 1) < NT;
        if (more) {
            const float* pa = Ag + (ch + 1) * BK3;
            const float* pw = Wg + (ch + 1) * BK3;
#pragma unroll
            for (int i = 0; i < 4; i++)
                astg[i] = *(const float4*)(pa + (size_t)(i * 64) * KDIM);
#pragma unroll
            for (int i = 0; i < 2; i++)
                bstg[i] = *(const float4*)(pw + (size_t)(i * 64) * KDIM);
        }
        const float* Ab = As + buf * A_BUF + warpM * LDK;
        const float* Wb = Bs + buf * B_BUF + warpN * LDK;

        // B fragments for both k-steps: one LDS.128 per ni
        float4 bf[8];
#pragma unroll
        for (int ni = 0; ni < 8; ni++)
            bf[ni] = *(const float4*)(Wb + (ni * 8 + r) * LDK + cc * 4);

#pragma unroll
        for (int mi = 0; mi < 4; mi++) {
            const float* ar = Ab + (mi * 16 + r) * LDK + cc * 4;
            float4 alo = *(const float4*)(ar);
            float4 ahi = *(const float4*)(ar + 8 * LDK);
            unsigned a0[4] = { __float_as_uint(alo.x), __float_as_uint(ahi.x),
                               __float_as_uint(alo.y), __float_as_uint(ahi.y) };
            unsigned a1[4] = { __float_as_uint(alo.z), __float_as_uint(ahi.z),
                               __float_as_uint(alo.w), __float_as_uint(ahi.w) };
#pragma unroll
            for (int ni = 0; ni < 8; ni++) {
                mma_tf32(c[mi][ni], a0, __float_as_uint(bf[ni].x), __float_as_uint(bf[ni].y));
                mma_tf32(c[mi][ni], a1, __float_as_uint(bf[ni].z), __float_as_uint(bf[ni].w));
            }
        }
        if (more) {
            const int nb = buf ^ 1;
            float* dstA = As + nb * A_BUF;
#pragma unroll
            for (int i = 0; i < 4; i++) {
                float* p = dstA + (sar + i * 64) * LDK + s;
                p[0]  = to_tf32(astg[i].x); p[4]  = to_tf32(astg[i].y);
                p[8]  = to_tf32(astg[i].z); p[12] = to_tf32(astg[i].w);
            }
            float* dstB = Bs + nb * B_BUF;
#pragma unroll
            for (int i = 0; i < 2; i++) {
                float* p = dstB + (sar + i * 64) * LDK + s;
                p[0]  = to_tf32(bstg[i].x); p[4]  = to_tf32(bstg[i].y);
                p[8]  = to_tf32(bstg[i].z); p[12] = to_tf32(bstg[i].w);
            }
            __syncthreads();
        }
    }

    // epilogue: bias + float2 stores
#pragma unroll
    for (int mi = 0; mi < 4; mi++) {
        int row0 = bm + warpM + mi * 16 + r;
#pragma unroll
        for (int ni = 0; ni < 8; ni++) {
            int col = bn + warpN + ni * 8 + cc * 2;
            float2 b2 = *(const float2*)(bias + col);
            *(float2*)(C + (size_t)row0 * Ntot + col) =
                make_float2(c[mi][ni][0] + b2.x, c[mi][ni][1] + b2.y);
            *(float2*)(C + (size_t)(row0 + 8) * Ntot + col) =
                make_float2(c[mi][ni][2] + b2.x, c[mi][ni][3] + b2.y);
        }
    }
}

// ---------------- attention v3: att row in registers ----------------
__global__ void __launch_bounds__(64)
attn3(const float* __restrict__ logit_scale) {
    const int bh = blockIdx.x;
    const int b = bh / NH;
    const int h = bh - b * NH;
    const int tid = threadIdx.x;

    __shared__ float ks[NTOK * 36];
    __shared__ float vs[NTOK * 36];
    __shared__ float bmx[NN];
    __shared__ float fk[NTOK];

    const float* base = g_qkv + (size_t)b * NTOK * QKV_N + h * HD;
    for (int e = tid; e < NTOK * 8; e += 64) {
        int r = e >> 3, q4 = (e & 7) * 4;
        *(float4*)(ks + r * 36 + q4) = *(const float4*)(base + (size_t)r * QKV_N + DIM + q4);
        *(float4*)(vs + r * 36 + q4) = *(const float4*)(base + (size_t)r * QKV_N + 2 * DIM + q4);
    }
    const float* bmg = g_biasmask + (size_t)((b & (NWMASK - 1)) * NH + h) * NN;
    for (int e = tid; e < NN; e += 64) bmx[e] = bmg[e];
    __syncthreads();

    if (tid < NTOK) {
        float sx = 0.0f;
#pragma unroll
        for (int d = 0; d < HD; d++) { float k = ks[tid * 36 + d]; sx += k * k; }
        fk[tid] = 1.0f / fmaxf(sqrtf(sx), 1e-12f);
    }
    __syncthreads();

    const int i = tid;
    if (i < NTOK) {
        float qf[HD];
        const float* qg = base + (size_t)i * QKV_N;
#pragma unroll
        for (int t = 0; t < 8; t++)
            *(float4*)(qf + t * 4) = *(const float4*)(qg + t * 4);
        float sq = 0.0f;
#pragma unroll
        for (int d = 0; d < HD; d++) sq += qf[d] * qf[d];
        float scale = expf(fminf(logit_scale[h], 4.605170185988091f));
        float fs = scale / fmaxf(sqrtf(sq), 1e-12f);
        unsigned long long qp[16];
#pragma unroll
        for (int t = 0; t < 16; t++) qp[t] = pack2(qf[2 * t] * fs, qf[2 * t + 1] * fs);

        float arow[NTOK];
        const float* bmrow = bmx + i * NTOK;
#pragma unroll
        for (int j = 0; j < NTOK; j++) {
            const ulonglong2* kr = (const ulonglong2*)(ks + j * 36);
            unsigned long long a0 = 0ull, a1 = 0ull, a2 = 0ull, a3 = 0ull;
#pragma unroll
            for (int t = 0; t < 4; t++) {
                ulonglong2 k0 = kr[2 * t];
                ulonglong2 k1 = kr[2 * t + 1];
                a0 = fma2(qp[4 * t + 0], k0.x, a0);
                a1 = fma2(qp[4 * t + 1], k0.y, a1);
                a2 = fma2(qp[4 * t + 2], k1.x, a2);
                a3 = fma2(qp[4 * t + 3], k1.y, a3);
            }
            float2 av = unpack2(add2(add2(a0, a1), add2(a2, a3)));
            arow[j] = (av.x + av.y) * fk[j] + bmrow[j];
        }

        float m = -1e30f;
#pragma unroll
        for (int j = 0; j < NTOK; j++) m = fmaxf(m, arow[j]);
        float sum = 0.0f;
#pragma unroll
        for (int j = 0; j < NTOK; j++) {
            float e = __expf(arow[j] - m);
            arow[j] = e;
            sum += e;
        }
        float inv = 1.0f / sum;

        unsigned long long o[16];
#pragma unroll
        for (int t = 0; t < 16; t++) o[t] = 0ull;
#pragma unroll
        for (int j = 0; j < NTOK; j++) {
            float a = arow[j];
            unsigned long long pa = pack2(a, a);
            const ulonglong2* vr = (const ulonglong2*)(vs + j * 36);
#pragma unroll
            for (int t = 0; t < 8; t++) {
                ulonglong2 vv = vr[t];
                o[2 * t]     = fma2(pa, vv.x, o[2 * t]);
                o[2 * t + 1] = fma2(pa, vv.y, o[2 * t + 1]);
            }
        }
        float* orow = g_attout + ((size_t)b * NTOK + i) * DIM + h * HD;
#pragma unroll
        for (int t = 0; t < 8; t++) {
            float2 lo = unpack2(o[2 * t]);
            float2 hi = unpack2(o[2 * t + 1]);
            *(float4*)(orow + t * 4) =
                make_float4(lo.x * inv, lo.y * inv, hi.x * inv, hi.y * inv);
        }
    }
}

// ---------------- launch ----------------
extern "C" void kernel_launch(void* const* d_in, const int* in_sizes, int n_in,
                              void* d_out, int out_size) {
    const float* x           = (const float*)d_in[0];
    const float* mask        = (const float*)d_in[1];
    const float* qkv_w       = (const float*)d_in[2];
    const float* q_bias      = (const float*)d_in[3];
    const float* v_bias      = (const float*)d_in[4];
    const float* logit_scale = (const float*)d_in[5];
    const float* cpb_w1      = (const float*)d_in[6];
    const float* cpb_b1      = (const float*)d_in[7];
    const float* cpb_w2      = (const float*)d_in[8];
    const float* proj_w      = (const float*)d_in[9];
    const float* proj_b      = (const float*)d_in[10];
    const float* rel_table   = (const float*)d_in[11];
    const int*   rel_idx     = (const int*)d_in[12];
    float* out = (float*)d_out;

    float* qkv_scratch;  cudaGetSymbolAddress((void**)&qkv_scratch, g_qkv);
    float* att_scratch;  cudaGetSymbolAddress((void**)&att_scratch, g_attout);
    float* qkv_bias_ptr; cudaGetSymbolAddress((void**)&qkv_bias_ptr, g_qkv_bias);

    cudaFuncSetAttribute(gemm_v3, cudaFuncAttributeMaxDynamicSharedMemorySize, GSMEM);

    build_qkv_bias<<<(QKV_N + 255) / 256, 256>>>(q_bias, v_bias);
    cpb_table_kernel<<<(TBL * NH + 255) / 256, 256>>>(rel_table, cpb_w1, cpb_b1, cpb_w2);
    biasmask_kernel<<<(NWMASK * NH * NN + 255) / 256, 256>>>(mask, rel_idx);

    // QKV GEMM: [100352,1152] = x @ qkv_w^T + bias
    {
        dim3 grid(QKV_N / BN3, MROWS / BM3);
        gemm_v3<<<grid, 256, GSMEM>>>(x, qkv_w, qkv_bias_ptr, qkv_scratch, QKV_N);
    }

    attn3<<<B_WIN * NH, 64>>>(logit_scale);

    // proj GEMM: out = attout @ proj_w^T + proj_b
    {
        dim3 grid(DIM / BN3, MROWS / BM3);
        gemm_v3<<<grid, 256, GSMEM>>>(att_scratch, proj_w, proj_b, out, DIM);
    }
}

// round 6
// speedup vs baseline: 3.5368x; 1.4906x over previous
#include <cuda_runtime.h>
#include <cuda_fp16.h>
#include <math.h>
#include <stdint.h>

// ---------------- problem constants ----------------
#define B_WIN   2048
#define NTOK    49
#define DIM     384
#define NH      12
#define HD      32
#define NWMASK  64
#define TBL     169
#define CPBH    512
#define QKV_N   1152
#define MROWS   (B_WIN * NTOK)    // 100352
#define NN      (NTOK * NTOK)     // 2401
#define KDIM    384

// ---------------- scratch (device globals) ----------------
__device__ float  g_qkv[(size_t)MROWS * QKV_N];     // f32 QKV output
__device__ __half g_xh[(size_t)MROWS * KDIM];       // x in half
__device__ __half g_atth[(size_t)MROWS * DIM];      // attention out in half
__device__ __half g_wh[(size_t)QKV_N * KDIM];       // qkv_w in half
__device__ __half g_pwh[(size_t)DIM * KDIM];        // proj_w in half
__device__ float  g_bias_table[TBL * NH];
__device__ float  g_qkv_bias[QKV_N];
__device__ float  g_biasmask[(size_t)NWMASK * NH * NN];

// ---------------- helpers ----------------
__device__ __forceinline__ uint32_t smem_u32(const void* p) {
    uint32_t a;
    asm("{ .reg .u64 t; cvta.to.shared.u64 t, %1; cvt.u32.u64 %0, t; }" : "=r"(a) : "l"(p));
    return a;
}
__device__ __forceinline__ unsigned long long fma2(unsigned long long a,
                                                   unsigned long long b,
                                                   unsigned long long c) {
    unsigned long long d;
    asm("fma.rn.f32x2 %0, %1, %2, %3;" : "=l"(d) : "l"(a), "l"(b), "l"(c));
    return d;
}
__device__ __forceinline__ unsigned long long add2(unsigned long long a,
                                                   unsigned long long b) {
    unsigned long long d;
    asm("add.rn.f32x2 %0, %1, %2;" : "=l"(d) : "l"(a), "l"(b));
    return d;
}
__device__ __forceinline__ unsigned long long pack2(float lo, float hi) {
    unsigned long long d;
    asm("mov.b64 %0, {%1, %2};" : "=l"(d) : "f"(lo), "f"(hi));
    return d;
}
__device__ __forceinline__ float2 unpack2(unsigned long long v) {
    float2 r;
    asm("mov.b64 {%0, %1}, %2;" : "=f"(r.x), "=f"(r.y) : "l"(v));
    return r;
}

// ---------------- prep kernels ----------------
__global__ void f32_to_h(const float* __restrict__ src, __half* __restrict__ dst, int n4) {
    int i = blockIdx.x * blockDim.x + threadIdx.x;
    int stride = gridDim.x * blockDim.x;
    for (; i < n4; i += stride) {
        float4 v = ((const float4*)src)[i];
        __half2 h0 = __floats2half2_rn(v.x, v.y);
        __half2 h1 = __floats2half2_rn(v.z, v.w);
        ((__half2*)dst)[2 * i]     = h0;
        ((__half2*)dst)[2 * i + 1] = h1;
    }
}

__global__ void build_qkv_bias(const float* __restrict__ q_bias,
                               const float* __restrict__ v_bias) {
    int n = blockIdx.x * blockDim.x + threadIdx.x;
    if (n >= QKV_N) return;
    float b;
    if (n < DIM)          b = q_bias[n];
    else if (n < 2 * DIM) b = 0.0f;
    else                  b = v_bias[n - 2 * DIM];
    g_qkv_bias[n] = b;
}

__global__ void cpb_table_kernel(const float* __restrict__ table,
                                 const float* __restrict__ w1,
                                 const float* __restrict__ b1,
                                 const float* __restrict__ w2) {
    int id = blockIdx.x * blockDim.x + threadIdx.x;
    if (id >= TBL * NH) return;
    int t = id / NH;
    int h = id % NH;
    float c0 = table[t * 2 + 0];
    float c1 = table[t * 2 + 1];
    const float* w2h = w2 + h * CPBH;
    float acc = 0.0f;
    for (int j = 0; j < CPBH; j++) {
        float hid = fmaxf(c0 * w1[j * 2 + 0] + c1 * w1[j * 2 + 1] + b1[j], 0.0f);
        acc += hid * w2h[j];
    }
    g_bias_table[t * NH + h] = 16.0f / (1.0f + expf(-acc));
}

__global__ void biasmask_kernel(const float* __restrict__ mask,
                                const int* __restrict__ rel_idx) {
    int e = blockIdx.x * 256 + threadIdx.x;
    if (e >= NWMASK * NH * NN) return;
    int wh = e / NN;
    int ij = e - wh * NN;
    int w = wh / NH;
    int h = wh - w * NH;
    g_biasmask[e] = g_bias_table[rel_idx[ij] * NH + h] + mask[(size_t)w * NN + ij];
}

// ---------------- fp16 mma.sync GEMM ----------------
// C[M,Ntot] = A[M,384]h @ W[Ntot,384]h^T + bias  (f32 accumulate)
// block 256x128, warp tile 64x64 (8 warps), BK=32 halfs, double-buffered smem.
// Smem rows padded to 40 halfs (80B) -> ldmatrix conflict-free.
#define LDH    40
#define A_BUFH (256 * LDH)   // 10240 halfs
#define B_BUFH (128 * LDH)   // 5120 halfs
#define GSMEM  ((A_BUFH + B_BUFH) * 2 * 2)  // 61440 bytes

__device__ __forceinline__ void mma_f16(float* c, const unsigned* a,
                                        unsigned b0, unsigned b1) {
    asm volatile(
        "mma.sync.aligned.m16n8k16.row.col.f32.f16.f16.f32 "
        "{%0,%1,%2,%3}, {%4,%5,%6,%7}, {%8,%9}, {%0,%1,%2,%3};"
        : "+f"(c[0]), "+f"(c[1]), "+f"(c[2]), "+f"(c[3])
        : "r"(a[0]), "r"(a[1]), "r"(a[2]), "r"(a[3]), "r"(b0), "r"(b1));
}
__device__ __forceinline__ void ldsm_x4(unsigned* r, uint32_t addr) {
    asm volatile("ldmatrix.sync.aligned.m8n8.x4.shared.b16 {%0,%1,%2,%3}, [%4];"
                 : "=r"(r[0]), "=r"(r[1]), "=r"(r[2]), "=r"(r[3]) : "r"(addr));
}

__global__ void __launch_bounds__(256, 1)
gemm_h(const __half* __restrict__ A, const __half* __restrict__ W,
       const float* __restrict__ bias, float* __restrict__ C, int Ntot) {
    extern __shared__ __half smh[];
    __half* Ab0 = smh;
    __half* Ab1 = smh + A_BUFH;
    __half* Bb0 = smh + 2 * A_BUFH;
    __half* Bb1 = smh + 2 * A_BUFH + B_BUFH;

    const int tid  = threadIdx.x;
    const int lane = tid & 31;
    const int wid  = tid >> 5;
    const int warpM = (wid >> 1) * 64;
    const int warpN = (wid & 1) * 64;
    const int bm = blockIdx.y * 256;
    const int bn = blockIdx.x * 128;

    // staging: thread covers 16B unit (un) of row (sr); A: rows sr+64i, B: rows sr(<128)+64i
    const int sr = tid >> 2;
    const int un = tid & 3;
    const __half* Ag = A + (size_t)(bm + sr) * KDIM + un * 8;
    const __half* Wg = W + (size_t)(bn + sr) * KDIM + un * 8;
    const int sAoff = sr * LDH + un * 8;

    float c[4][8][4];
#pragma unroll
    for (int mi = 0; mi < 4; mi++)
#pragma unroll
        for (int ni = 0; ni < 8; ni++)
#pragma unroll
            for (int e = 0; e < 4; e++) c[mi][ni][e] = 0.0f;

    // ldmatrix base addresses (bytes)
    const int aRow = (lane & 7) + ((lane >> 3) & 1) * 8;
    const int aCol = ((lane >> 4) & 1) * 8;
    const int bRow = (lane & 7) + ((lane >> 4) & 1) * 8;
    const int bCol = ((lane >> 3) & 1) * 8;
    uint32_t aBase[2], bBase[2];
    aBase[0] = smem_u32(Ab0 + (warpM + aRow) * LDH + aCol);
    aBase[1] = smem_u32(Ab1 + (warpM + aRow) * LDH + aCol);
    bBase[0] = smem_u32(Bb0 + (warpN + bRow) * LDH + bCol);
    bBase[1] = smem_u32(Bb1 + (warpN + bRow) * LDH + bCol);

    uint4 av[4], bv[2];
    // prologue: stage chunk 0 into buffer 0
#pragma unroll
    for (int i = 0; i < 4; i++)
        av[i] = *(const uint4*)(Ag + (size_t)(i * 64) * KDIM);
#pragma unroll
    for (int i = 0; i < 2; i++)
        bv[i] = *(const uint4*)(Wg + (size_t)(i * 64) * KDIM);
#pragma unroll
    for (int i = 0; i < 4; i++)
        *(uint4*)(Ab0 + sAoff + i * 64 * LDH) = av[i];
#pragma unroll
    for (int i = 0; i < 2; i++)
        *(uint4*)(Bb0 + sAoff + i * 64 * LDH) = bv[i];
    __syncthreads();

    const int NT = KDIM / 32;   // 12 chunks of 32 halfs
    for (int ch = 0; ch < NT; ch++) {
        const int buf = ch & 1;
        const bool more = (ch + 1) < NT;
        if (more) {
            const __half* pa = Ag + (ch + 1) * 32;
            const __half* pw = Wg + (ch + 1) * 32;
#pragma unroll
            for (int i = 0; i < 4; i++)
                av[i] = *(const uint4*)(pa + (size_t)(i * 64) * KDIM);
#pragma unroll
            for (int i = 0; i < 2; i++)
                bv[i] = *(const uint4*)(pw + (size_t)(i * 64) * KDIM);
        }
#pragma unroll
        for (int s = 0; s < 2; s++) {
            unsigned af[4][4], bf[4][4];
#pragma unroll
            for (int mi = 0; mi < 4; mi++)
                ldsm_x4(af[mi], aBase[buf] + mi * (16 * LDH * 2) + s * 32);
#pragma unroll
            for (int p = 0; p < 4; p++)
                ldsm_x4(bf[p], bBase[buf] + p * (16 * LDH * 2) + s * 32);
#pragma unroll
            for (int mi = 0; mi < 4; mi++)
#pragma unroll
                for (int p = 0; p < 4; p++) {
                    mma_f16(c[mi][2 * p],     af[mi], bf[p][0], bf[p][1]);
                    mma_f16(c[mi][2 * p + 1], af[mi], bf[p][2], bf[p][3]);
                }
        }
        if (more) {
            __syncthreads();   // all warps done reading buf^1 from previous round
            __half* dA = buf ? Ab0 : Ab1;
            __half* dB = buf ? Bb0 : Bb1;
#pragma unroll
            for (int i = 0; i < 4; i++)
                *(uint4*)(dA + sAoff + i * 64 * LDH) = av[i];
#pragma unroll
            for (int i = 0; i < 2; i++)
                *(uint4*)(dB + sAoff + i * 64 * LDH) = bv[i];
            __syncthreads();
        }
    }

    // epilogue: bias + float2 stores
    const int r  = lane >> 2;
    const int cc = lane & 3;
#pragma unroll
    for (int mi = 0; mi < 4; mi++) {
        int row0 = bm + warpM + mi * 16 + r;
#pragma unroll
        for (int ni = 0; ni < 8; ni++) {
            int col = bn + warpN + ni * 8 + cc * 2;
            float2 b2 = *(const float2*)(bias + col);
            *(float2*)(C + (size_t)row0 * Ntot + col) =
                make_float2(c[mi][ni][0] + b2.x, c[mi][ni][1] + b2.y);
            *(float2*)(C + (size_t)(row0 + 8) * Ntot + col) =
                make_float2(c[mi][ni][2] + b2.x, c[mi][ni][3] + b2.y);
        }
    }
}

// ---------------- attention (f32 math, half output) ----------------
__global__ void __launch_bounds__(64)
attn4(const float* __restrict__ logit_scale) {
    const int bh = blockIdx.x;
    const int b = bh / NH;
    const int h = bh - b * NH;
    const int tid = threadIdx.x;

    __shared__ float ks[NTOK * 36];
    __shared__ float vs[NTOK * 36];
    __shared__ float bmx[NN];
    __shared__ float fk[NTOK];

    const float* base = g_qkv + (size_t)b * NTOK * QKV_N + h * HD;
    for (int e = tid; e < NTOK * 8; e += 64) {
        int r = e >> 3, q4 = (e & 7) * 4;
        *(float4*)(ks + r * 36 + q4) = *(const float4*)(base + (size_t)r * QKV_N + DIM + q4);
        *(float4*)(vs + r * 36 + q4) = *(const float4*)(base + (size_t)r * QKV_N + 2 * DIM + q4);
    }
    const float* bmg = g_biasmask + (size_t)((b & (NWMASK - 1)) * NH + h) * NN;
    for (int e = tid; e < NN; e += 64) bmx[e] = bmg[e];
    __syncthreads();

    if (tid < NTOK) {
        float sx = 0.0f;
#pragma unroll
        for (int d = 0; d < HD; d++) { float k = ks[tid * 36 + d]; sx += k * k; }
        fk[tid] = 1.0f / fmaxf(sqrtf(sx), 1e-12f);
    }
    __syncthreads();

    const int i = tid;
    if (i < NTOK) {
        float qf[HD];
        const float* qg = base + (size_t)i * QKV_N;
#pragma unroll
        for (int t = 0; t < 8; t++)
            *(float4*)(qf + t * 4) = *(const float4*)(qg + t * 4);
        float sq = 0.0f;
#pragma unroll
        for (int d = 0; d < HD; d++) sq += qf[d] * qf[d];
        float scale = expf(fminf(logit_scale[h], 4.605170185988091f));
        float fs = scale / fmaxf(sqrtf(sq), 1e-12f);
        unsigned long long qp[16];
#pragma unroll
        for (int t = 0; t < 16; t++) qp[t] = pack2(qf[2 * t] * fs, qf[2 * t + 1] * fs);

        float arow[NTOK];
        const float* bmrow = bmx + i * NTOK;
#pragma unroll
        for (int j = 0; j < NTOK; j++) {
            const ulonglong2* kr = (const ulonglong2*)(ks + j * 36);
            unsigned long long a0 = 0ull, a1 = 0ull, a2 = 0ull, a3 = 0ull;
#pragma unroll
            for (int t = 0; t < 4; t++) {
                ulonglong2 k0 = kr[2 * t];
                ulonglong2 k1 = kr[2 * t + 1];
                a0 = fma2(qp[4 * t + 0], k0.x, a0);
                a1 = fma2(qp[4 * t + 1], k0.y, a1);
                a2 = fma2(qp[4 * t + 2], k1.x, a2);
                a3 = fma2(qp[4 * t + 3], k1.y, a3);
            }
            float2 av = unpack2(add2(add2(a0, a1), add2(a2, a3)));
            arow[j] = (av.x + av.y) * fk[j] + bmrow[j];
        }

        float m = -1e30f;
#pragma unroll
        for (int j = 0; j < NTOK; j++) m = fmaxf(m, arow[j]);
        float sum = 0.0f;
#pragma unroll
        for (int j = 0; j < NTOK; j++) {
            float e = __expf(arow[j] - m);
            arow[j] = e;
            sum += e;
        }
        float inv = 1.0f / sum;

        unsigned long long o[16];
#pragma unroll
        for (int t = 0; t < 16; t++) o[t] = 0ull;
#pragma unroll
        for (int j = 0; j < NTOK; j++) {
            float a = arow[j];
            unsigned long long pa = pack2(a, a);
            const ulonglong2* vr = (const ulonglong2*)(vs + j * 36);
#pragma unroll
            for (int t = 0; t < 8; t++) {
                ulonglong2 vv = vr[t];
                o[2 * t]     = fma2(pa, vv.x, o[2 * t]);
                o[2 * t + 1] = fma2(pa, vv.y, o[2 * t + 1]);
            }
        }
        __half* orow = g_atth + ((size_t)b * NTOK + i) * DIM + h * HD;
#pragma unroll
        for (int t = 0; t < 8; t++) {
            float2 lo = unpack2(o[2 * t]);
            float2 hi = unpack2(o[2 * t + 1]);
            __half2 h0 = __floats2half2_rn(lo.x * inv, lo.y * inv);
            __half2 h1 = __floats2half2_rn(hi.x * inv, hi.y * inv);
            *(__half2*)(orow + t * 4)     = h0;
            *(__half2*)(orow + t * 4 + 2) = h1;
        }
    }
}

// ---------------- launch ----------------
extern "C" void kernel_launch(void* const* d_in, const int* in_sizes, int n_in,
                              void* d_out, int out_size) {
    const float* x           = (const float*)d_in[0];
    const float* mask        = (const float*)d_in[1];
    const float* qkv_w       = (const float*)d_in[2];
    const float* q_bias      = (const float*)d_in[3];
    const float* v_bias      = (const float*)d_in[4];
    const float* logit_scale = (const float*)d_in[5];
    const float* cpb_w1      = (const float*)d_in[6];
    const float* cpb_b1      = (const float*)d_in[7];
    const float* cpb_w2      = (const float*)d_in[8];
    const float* proj_w      = (const float*)d_in[9];
    const float* proj_b      = (const float*)d_in[10];
    const float* rel_table   = (const float*)d_in[11];
    const int*   rel_idx     = (const int*)d_in[12];
    float* out = (float*)d_out;

    float*  qkv_scratch;  cudaGetSymbolAddress((void**)&qkv_scratch, g_qkv);
    __half* xh;           cudaGetSymbolAddress((void**)&xh, g_xh);
    __half* atth;         cudaGetSymbolAddress((void**)&atth, g_atth);
    __half* wh;           cudaGetSymbolAddress((void**)&wh, g_wh);
    __half* pwh;          cudaGetSymbolAddress((void**)&pwh, g_pwh);
    float*  qkv_bias_ptr; cudaGetSymbolAddress((void**)&qkv_bias_ptr, g_qkv_bias);

    cudaFuncSetAttribute(gemm_h, cudaFuncAttributeMaxDynamicSharedMemorySize, GSMEM);

    // prep + conversions
    f32_to_h<<<1184, 256>>>(x, xh, MROWS * KDIM / 4);
    f32_to_h<<<432, 256>>>(qkv_w, wh, QKV_N * KDIM / 4);
    f32_to_h<<<144, 256>>>(proj_w, pwh, DIM * KDIM / 4);
    build_qkv_bias<<<(QKV_N + 255) / 256, 256>>>(q_bias, v_bias);
    cpb_table_kernel<<<(TBL * NH + 255) / 256, 256>>>(rel_table, cpb_w1, cpb_b1, cpb_w2);
    biasmask_kernel<<<(NWMASK * NH * NN + 255) / 256, 256>>>(mask, rel_idx);

    // QKV GEMM: [100352,1152] = x @ qkv_w^T + bias (fp16 in, f32 out)
    {
        dim3 grid(QKV_N / 128, MROWS / 256);
        gemm_h<<<grid, 256, GSMEM>>>(xh, wh, qkv_bias_ptr, qkv_scratch, QKV_N);
    }

    attn4<<<B_WIN * NH, 64>>>(logit_scale);

    // proj GEMM: out = attout @ proj_w^T + proj_b
    {
        dim3 grid(DIM / 128, MROWS / 256);
        gemm_h<<<grid, 256, GSMEM>>>(atth, pwh, proj_b, out, DIM);
    }
}

// round 7
// speedup vs baseline: 3.7887x; 1.0712x over previous
#include <cuda_runtime.h>
#include <cuda_fp16.h>
#include <math.h>
#include <stdint.h>

// ---------------- problem constants ----------------
#define B_WIN   2048
#define NTOK    49
#define DIM     384
#define NH      12
#define HD      32
#define NWMASK  64
#define TBL     169
#define CPBH    512
#define QKV_N   1152
#define MROWS   (B_WIN * NTOK)    // 100352
#define NN      (NTOK * NTOK)     // 2401
#define KDIM    384

// ---------------- scratch (device globals) ----------------
__device__ float  g_qkv[(size_t)MROWS * QKV_N];
__device__ __half g_xh[(size_t)MROWS * KDIM];
__device__ __half g_atth[(size_t)MROWS * DIM];
__device__ __half g_wh[(size_t)QKV_N * KDIM];
__device__ __half g_pwh[(size_t)DIM * KDIM];
__device__ float  g_bias_table[TBL * NH];
__device__ float  g_qkv_bias[QKV_N];
__device__ float  g_biasmask[(size_t)NWMASK * NH * NN];

// ---------------- helpers ----------------
__device__ __forceinline__ uint32_t smem_u32(const void* p) {
    uint32_t a;
    asm("{ .reg .u64 t; cvta.to.shared.u64 t, %1; cvt.u32.u64 %0, t; }" : "=r"(a) : "l"(p));
    return a;
}
__device__ __forceinline__ unsigned long long fma2(unsigned long long a,
                                                   unsigned long long b,
                                                   unsigned long long c) {
    unsigned long long d;
    asm("fma.rn.f32x2 %0, %1, %2, %3;" : "=l"(d) : "l"(a), "l"(b), "l"(c));
    return d;
}
__device__ __forceinline__ unsigned long long add2(unsigned long long a,
                                                   unsigned long long b) {
    unsigned long long d;
    asm("add.rn.f32x2 %0, %1, %2;" : "=l"(d) : "l"(a), "l"(b));
    return d;
}
__device__ __forceinline__ unsigned long long pack2(float lo, float hi) {
    unsigned long long d;
    asm("mov.b64 %0, {%1, %2};" : "=l"(d) : "f"(lo), "f"(hi));
    return d;
}
__device__ __forceinline__ float2 unpack2(unsigned long long v) {
    float2 r;
    asm("mov.b64 {%0, %1}, %2;" : "=f"(r.x), "=f"(r.y) : "l"(v));
    return r;
}
__device__ __forceinline__ void cp16(uint32_t dst, const void* src) {
    asm volatile("cp.async.ca.shared.global [%0], [%1], 16;" :: "r"(dst), "l"(src));
}
#define CP_COMMIT() asm volatile("cp.async.commit_group;" ::: "memory")
#define CP_WAIT1()  asm volatile("cp.async.wait_group 1;" ::: "memory")

// ---------------- fused prep ----------------
#define N_CVTX (MROWS * KDIM / 4)           // 9633792 float4 items
#define N_CVTW (QKV_N * KDIM / 4)           // 110592
#define N_CVTP (DIM * KDIM / 4)             // 36864
#define N_BIAS QKV_N                        // 1152
#define N_CPB  (TBL * NH)                   // 2028
#define N_TOT  (N_CVTX + N_CVTW + N_CVTP + N_BIAS + N_CPB)

__global__ void prep_fused(const float* __restrict__ x,
                           const float* __restrict__ qkv_w,
                           const float* __restrict__ proj_w,
                           const float* __restrict__ q_bias,
                           const float* __restrict__ v_bias,
                           const float* __restrict__ table,
                           const float* __restrict__ w1,
                           const float* __restrict__ b1,
                           const float* __restrict__ w2) {
    long long id = (long long)blockIdx.x * blockDim.x + threadIdx.x;
    if (id < N_CVTX) {
        float4 v = ((const float4*)x)[id];
        ((__half2*)g_xh)[2 * id]     = __floats2half2_rn(v.x, v.y);
        ((__half2*)g_xh)[2 * id + 1] = __floats2half2_rn(v.z, v.w);
        return;
    }
    id -= N_CVTX;
    if (id < N_CVTW) {
        float4 v = ((const float4*)qkv_w)[id];
        ((__half2*)g_wh)[2 * id]     = __floats2half2_rn(v.x, v.y);
        ((__half2*)g_wh)[2 * id + 1] = __floats2half2_rn(v.z, v.w);
        return;
    }
    id -= N_CVTW;
    if (id < N_CVTP) {
        float4 v = ((const float4*)proj_w)[id];
        ((__half2*)g_pwh)[2 * id]     = __floats2half2_rn(v.x, v.y);
        ((__half2*)g_pwh)[2 * id + 1] = __floats2half2_rn(v.z, v.w);
        return;
    }
    id -= N_CVTP;
    if (id < N_BIAS) {
        int n = (int)id;
        float b;
        if (n < DIM)          b = q_bias[n];
        else if (n < 2 * DIM) b = 0.0f;
        else                  b = v_bias[n - 2 * DIM];
        g_qkv_bias[n] = b;
        return;
    }
    id -= N_BIAS;
    if (id < N_CPB) {
        int t = (int)id / NH;
        int h = (int)id % NH;
        float c0 = table[t * 2 + 0];
        float c1 = table[t * 2 + 1];
        const float* w2h = w2 + h * CPBH;
        float acc = 0.0f;
        for (int j = 0; j < CPBH; j++) {
            float hid = fmaxf(c0 * w1[j * 2 + 0] + c1 * w1[j * 2 + 1] + b1[j], 0.0f);
            acc += hid * w2h[j];
        }
        g_bias_table[t * NH + h] = 16.0f / (1.0f + expf(-acc));
    }
}

__global__ void biasmask_kernel(const float* __restrict__ mask,
                                const int* __restrict__ rel_idx) {
    int e = blockIdx.x * 256 + threadIdx.x;
    if (e >= NWMASK * NH * NN) return;
    int wh = e / NN;
    int ij = e - wh * NN;
    int w = wh / NH;
    int h = wh - w * NH;
    g_biasmask[e] = g_bias_table[rel_idx[ij] * NH + h] + mask[(size_t)w * NN + ij];
}

// ---------------- fp16 mma.sync GEMM, cp.async 3-stage ----------------
// C[M,Ntot] = A[M,384]h @ W[Ntot,384]h^T + bias (f32 accum)
// block 256x128, warp tile 64x64 (8 warps), BK=32 halfs, 3 pipeline stages.
#define LDH     40
#define A_ST    (256 * LDH)      // 10240 halfs per stage
#define B_ST    (128 * LDH)      // 5120 halfs
#define STAGE_H (A_ST + B_ST)    // 15360 halfs
#define GSMEM   (3 * STAGE_H * 2)  // 92160 bytes

__device__ __forceinline__ void mma_f16(float* c, const unsigned* a,
                                        unsigned b0, unsigned b1) {
    asm volatile(
        "mma.sync.aligned.m16n8k16.row.col.f32.f16.f16.f32 "
        "{%0,%1,%2,%3}, {%4,%5,%6,%7}, {%8,%9}, {%0,%1,%2,%3};"
        : "+f"(c[0]), "+f"(c[1]), "+f"(c[2]), "+f"(c[3])
        : "r"(a[0]), "r"(a[1]), "r"(a[2]), "r"(a[3]), "r"(b0), "r"(b1));
}
__device__ __forceinline__ void ldsm_x4(unsigned* r, uint32_t addr) {
    asm volatile("ldmatrix.sync.aligned.m8n8.x4.shared.b16 {%0,%1,%2,%3}, [%4];"
                 : "=r"(r[0]), "=r"(r[1]), "=r"(r[2]), "=r"(r[3]) : "r"(addr));
}

__global__ void __launch_bounds__(256, 1)
gemm_h2(const __half* __restrict__ A, const __half* __restrict__ W,
        const float* __restrict__ bias, float* __restrict__ C, int Ntot) {
    extern __shared__ __half smh[];
    const uint32_t sbase = smem_u32(smh);
    const int tid  = threadIdx.x;
    const int lane = tid & 31;
    const int wid  = tid >> 5;
    const int warpM = (wid >> 1) * 64;
    const int warpN = (wid & 1) * 64;
    const int bm = blockIdx.y * 256;
    const int bn = blockIdx.x * 128;

    // staging mapping: thread -> (row sr, 16B unit un)
    const int sr = tid >> 2;
    const int un = tid & 3;
    const __half* Ag = A + (size_t)(bm + sr) * KDIM + un * 8;
    const __half* Wg = W + (size_t)(bn + sr) * KDIM + un * 8;
    const uint32_t stgOff = (uint32_t)(sr * LDH + un * 8) * 2;

    float c[4][8][4];
#pragma unroll
    for (int mi = 0; mi < 4; mi++)
#pragma unroll
        for (int ni = 0; ni < 8; ni++)
#pragma unroll
            for (int e = 0; e < 4; e++) c[mi][ni][e] = 0.0f;

    // ldmatrix lane addressing
    const int aRow = (lane & 7) + ((lane >> 3) & 1) * 8;
    const int aCol = ((lane >> 4) & 1) * 8;
    const int bRow = (lane & 7) + ((lane >> 4) & 1) * 8;
    const int bCol = ((lane >> 3) & 1) * 8;
    const uint32_t aFrag = sbase + (uint32_t)((warpM + aRow) * LDH + aCol) * 2;
    const uint32_t bFrag = sbase + (uint32_t)(A_ST + (warpN + bRow) * LDH + bCol) * 2;

#define ISSUE(stg, ch) do { \
    uint32_t _b = sbase + (stg) * (STAGE_H * 2) + stgOff; \
    const __half* _a = Ag + (ch) * 32; \
    cp16(_b,                  _a); \
    cp16(_b + 64 * LDH * 2,   _a + (size_t)64 * KDIM); \
    cp16(_b + 128 * LDH * 2,  _a + (size_t)128 * KDIM); \
    cp16(_b + 192 * LDH * 2,  _a + (size_t)192 * KDIM); \
    const __half* _w = Wg + (ch) * 32; \
    uint32_t _bb = _b + A_ST * 2; \
    cp16(_bb,                 _w); \
    cp16(_bb + 64 * LDH * 2,  _w + (size_t)64 * KDIM); \
} while (0)

    ISSUE(0, 0); CP_COMMIT();
    ISSUE(1, 1); CP_COMMIT();

#pragma unroll
    for (int ch = 0; ch < 12; ch++) {
        const int stg = ch % 3;
        CP_WAIT1();
        __syncthreads();
        if (ch + 2 < 12) { ISSUE((ch + 2) % 3, ch + 2); }
        CP_COMMIT();

        const uint32_t aB = aFrag + stg * (STAGE_H * 2);
        const uint32_t bB = bFrag + stg * (STAGE_H * 2);
#pragma unroll
        for (int s2 = 0; s2 < 2; s2++) {
            unsigned af[4][4], bf[4][4];
#pragma unroll
            for (int mi = 0; mi < 4; mi++)
                ldsm_x4(af[mi], aB + mi * (16 * LDH * 2) + s2 * 32);
#pragma unroll
            for (int p = 0; p < 4; p++)
                ldsm_x4(bf[p], bB + p * (16 * LDH * 2) + s2 * 32);
#pragma unroll
            for (int mi = 0; mi < 4; mi++)
#pragma unroll
                for (int p = 0; p < 4; p++) {
                    mma_f16(c[mi][2 * p],     af[mi], bf[p][0], bf[p][1]);
                    mma_f16(c[mi][2 * p + 1], af[mi], bf[p][2], bf[p][3]);
                }
        }
    }
#undef ISSUE

    // epilogue
    const int r  = lane >> 2;
    const int cc = lane & 3;
#pragma unroll
    for (int mi = 0; mi < 4; mi++) {
        int row0 = bm + warpM + mi * 16 + r;
#pragma unroll
        for (int ni = 0; ni < 8; ni++) {
            int col = bn + warpN + ni * 8 + cc * 2;
            float2 b2 = *(const float2*)(bias + col);
            *(float2*)(C + (size_t)row0 * Ntot + col) =
                make_float2(c[mi][ni][0] + b2.x, c[mi][ni][1] + b2.y);
            *(float2*)(C + (size_t)(row0 + 8) * Ntot + col) =
                make_float2(c[mi][ni][2] + b2.x, c[mi][ni][3] + b2.y);
        }
    }
}

// ---------------- attention ----------------
__global__ void __launch_bounds__(64)
attn5(const float* __restrict__ logit_scale) {
    const int bh = blockIdx.x;
    const int b = bh / NH;
    const int h = bh - b * NH;
    const int tid = threadIdx.x;

    __shared__ float ks[NTOK * 36];
    __shared__ float vs[NTOK * 36];
    __shared__ float bmx[NN];
    __shared__ float fk[NTOK];

    const float* base = g_qkv + (size_t)b * NTOK * QKV_N + h * HD;
    for (int e = tid; e < NTOK * 8; e += 64) {
        int r = e >> 3, q4 = (e & 7) * 4;
        *(float4*)(ks + r * 36 + q4) = *(const float4*)(base + (size_t)r * QKV_N + DIM + q4);
        *(float4*)(vs + r * 36 + q4) = *(const float4*)(base + (size_t)r * QKV_N + 2 * DIM + q4);
    }
    const float* bmg = g_biasmask + (size_t)((b & (NWMASK - 1)) * NH + h) * NN;
    for (int e = tid; e < NN; e += 64) bmx[e] = bmg[e];
    __syncthreads();

    if (tid < NTOK) {
        float sx = 0.0f;
#pragma unroll
        for (int d = 0; d < HD; d++) { float k = ks[tid * 36 + d]; sx += k * k; }
        fk[tid] = 1.0f / fmaxf(sqrtf(sx), 1e-12f);
    }
    __syncthreads();

    const int i = tid;
    if (i < NTOK) {
        float qf[HD];
        const float* qg = base + (size_t)i * QKV_N;
#pragma unroll
        for (int t = 0; t < 8; t++)
            *(float4*)(qf + t * 4) = *(const float4*)(qg + t * 4);
        float sq = 0.0f;
#pragma unroll
        for (int d = 0; d < HD; d++) sq += qf[d] * qf[d];
        float scale = expf(fminf(logit_scale[h], 4.605170185988091f));
        float fs = scale / fmaxf(sqrtf(sq), 1e-12f);
        unsigned long long qp[16];
#pragma unroll
        for (int t = 0; t < 16; t++) qp[t] = pack2(qf[2 * t] * fs, qf[2 * t + 1] * fs);

        float arow[NTOK];
        const float* bmrow = bmx + i * NTOK;
#pragma unroll
        for (int j = 0; j < NTOK; j++) {
            const ulonglong2* kr = (const ulonglong2*)(ks + j * 36);
            unsigned long long a0 = 0ull, a1 = 0ull, a2 = 0ull, a3 = 0ull;
#pragma unroll
            for (int t = 0; t < 4; t++) {
                ulonglong2 k0 = kr[2 * t];
                ulonglong2 k1 = kr[2 * t + 1];
                a0 = fma2(qp[4 * t + 0], k0.x, a0);
                a1 = fma2(qp[4 * t + 1], k0.y, a1);
                a2 = fma2(qp[4 * t + 2], k1.x, a2);
                a3 = fma2(qp[4 * t + 3], k1.y, a3);
            }
            float2 av = unpack2(add2(add2(a0, a1), add2(a2, a3)));
            arow[j] = (av.x + av.y) * fk[j] + bmrow[j];
        }

        // softmax with 4-way split chains
        float m0 = -1e30f, m1 = -1e30f, m2 = -1e30f, m3 = -1e30f;
#pragma unroll
        for (int j = 0; j < 48; j += 4) {
            m0 = fmaxf(m0, arow[j]);
            m1 = fmaxf(m1, arow[j + 1]);
            m2 = fmaxf(m2, arow[j + 2]);
            m3 = fmaxf(m3, arow[j + 3]);
        }
        float m = fmaxf(fmaxf(fmaxf(m0, m1), fmaxf(m2, m3)), arow[48]);
        float s0 = 0.f, s1 = 0.f, s2 = 0.f, s3 = 0.f;
#pragma unroll
        for (int j = 0; j < 48; j += 4) {
            float e0 = __expf(arow[j] - m);     arow[j] = e0;     s0 += e0;
            float e1 = __expf(arow[j + 1] - m); arow[j + 1] = e1; s1 += e1;
            float e2 = __expf(arow[j + 2] - m); arow[j + 2] = e2; s2 += e2;
            float e3 = __expf(arow[j + 3] - m); arow[j + 3] = e3; s3 += e3;
        }
        float e48 = __expf(arow[48] - m); arow[48] = e48;
        float inv = 1.0f / ((s0 + s1) + (s2 + s3) + e48);

        unsigned long long o[16];
#pragma unroll
        for (int t = 0; t < 16; t++) o[t] = 0ull;
#pragma unroll
        for (int j = 0; j < NTOK; j++) {
            float a = arow[j];
            unsigned long long pa = pack2(a, a);
            const ulonglong2* vr = (const ulonglong2*)(vs + j * 36);
#pragma unroll
            for (int t = 0; t < 8; t++) {
                ulonglong2 vv = vr[t];
                o[2 * t]     = fma2(pa, vv.x, o[2 * t]);
                o[2 * t + 1] = fma2(pa, vv.y, o[2 * t + 1]);
            }
        }
        __half* orow = g_atth + ((size_t)b * NTOK + i) * DIM + h * HD;
#pragma unroll
        for (int t = 0; t < 8; t++) {
            float2 lo = unpack2(o[2 * t]);
            float2 hi = unpack2(o[2 * t + 1]);
            *(__half2*)(orow + t * 4)     = __floats2half2_rn(lo.x * inv, lo.y * inv);
            *(__half2*)(orow + t * 4 + 2) = __floats2half2_rn(hi.x * inv, hi.y * inv);
        }
    }
}

// ---------------- launch ----------------
extern "C" void kernel_launch(void* const* d_in, const int* in_sizes, int n_in,
                              void* d_out, int out_size) {
    const float* x           = (const float*)d_in[0];
    const float* mask        = (const float*)d_in[1];
    const float* qkv_w       = (const float*)d_in[2];
    const float* q_bias      = (const float*)d_in[3];
    const float* v_bias      = (const float*)d_in[4];
    const float* logit_scale = (const float*)d_in[5];
    const float* cpb_w1      = (const float*)d_in[6];
    const float* cpb_b1      = (const float*)d_in[7];
    const float* cpb_w2      = (const float*)d_in[8];
    const float* proj_w      = (const float*)d_in[9];
    const float* proj_b      = (const float*)d_in[10];
    const float* rel_table   = (const float*)d_in[11];
    const int*   rel_idx     = (const int*)d_in[12];
    float* out = (float*)d_out;

    float*  qkv_scratch;  cudaGetSymbolAddress((void**)&qkv_scratch, g_qkv);
    __half* xh;           cudaGetSymbolAddress((void**)&xh, g_xh);
    __half* atth;         cudaGetSymbolAddress((void**)&atth, g_atth);
    __half* wh;           cudaGetSymbolAddress((void**)&wh, g_wh);
    __half* pwh;          cudaGetSymbolAddress((void**)&pwh, g_pwh);
    float*  qkv_bias_ptr; cudaGetSymbolAddress((void**)&qkv_bias_ptr, g_qkv_bias);

    cudaFuncSetAttribute(gemm_h2, cudaFuncAttributeMaxDynamicSharedMemorySize, GSMEM);

    // launch 0: fused prep (conversions + qkv bias + CPB MLP)
    prep_fused<<<(N_TOT + 255) / 256, 256>>>(x, qkv_w, proj_w, q_bias, v_bias,
                                             rel_table, cpb_w1, cpb_b1, cpb_w2);
    // launch 1: fused bias+mask table
    biasmask_kernel<<<(NWMASK * NH * NN + 255) / 256, 256>>>(mask, rel_idx);

    // launch 2: QKV GEMM
    {
        dim3 grid(QKV_N / 128, MROWS / 256);
        gemm_h2<<<grid, 256, GSMEM>>>(xh, wh, qkv_bias_ptr, qkv_scratch, QKV_N);
    }

    // launch 3 (ncu profile slot): attention
    attn5<<<B_WIN * NH, 64>>>(logit_scale);

    // launch 4: proj GEMM
    {
        dim3 grid(DIM / 128, MROWS / 256);
        gemm_h2<<<grid, 256, GSMEM>>>(atth, pwh, proj_b, out, DIM);
    }
}

// round 9
// speedup vs baseline: 4.0837x; 1.0779x over previous
#include <cuda_runtime.h>
#include <cuda_fp16.h>
#include <math.h>
#include <stdint.h>

// ---------------- problem constants ----------------
#define B_WIN   2048
#define NTOK    49
#define DIM     384
#define NH      12
#define HD      32
#define NWMASK  64
#define TBL     169
#define CPBH    512
#define QKV_N   1152
#define MROWS   (B_WIN * NTOK)    // 100352
#define NN      (NTOK * NTOK)     // 2401
#define KDIM    384

// ---------------- scratch (device globals) ----------------
__device__ float  g_qkv[(size_t)MROWS * QKV_N];
__device__ __half g_xh[(size_t)MROWS * KDIM];
__device__ __half g_atth[(size_t)MROWS * DIM];
__device__ __half g_wh[(size_t)QKV_N * KDIM];
__device__ __half g_pwh[(size_t)DIM * KDIM];
__device__ float  g_bias_table[TBL * NH];
__device__ float  g_qkv_bias[QKV_N];
// bias+mask pre-arranged in mma C-fragment layout:
// [w][h][mi(4)][t(7)][lane(32)][4]  (c0,c1,c2,c3); -1e30 for pad rows/cols
#define BMF_PER_WH (4 * 7 * 128)
__device__ float  g_bmF[(size_t)NWMASK * NH * BMF_PER_WH];   // 11 MB

// ---------------- helpers ----------------
__device__ __forceinline__ uint32_t smem_u32(const void* p) {
    uint32_t a;
    asm("{ .reg .u64 t; cvta.to.shared.u64 t, %1; cvt.u32.u64 %0, t; }" : "=r"(a) : "l"(p));
    return a;
}
__device__ __forceinline__ void cp16(uint32_t dst, const void* src) {
    asm volatile("cp.async.ca.shared.global [%0], [%1], 16;" :: "r"(dst), "l"(src));
}
#define CP_COMMIT() asm volatile("cp.async.commit_group;" ::: "memory")
#define CP_WAIT1()  asm volatile("cp.async.wait_group 1;" ::: "memory")

__device__ __forceinline__ void mma_f16(float* c, const unsigned* a,
                                        unsigned b0, unsigned b1) {
    asm volatile(
        "mma.sync.aligned.m16n8k16.row.col.f32.f16.f16.f32 "
        "{%0,%1,%2,%3}, {%4,%5,%6,%7}, {%8,%9}, {%0,%1,%2,%3};"
        : "+f"(c[0]), "+f"(c[1]), "+f"(c[2]), "+f"(c[3])
        : "r"(a[0]), "r"(a[1]), "r"(a[2]), "r"(a[3]), "r"(b0), "r"(b1));
}
__device__ __forceinline__ void ldsm_x4(unsigned* r, uint32_t addr) {
    asm volatile("ldmatrix.sync.aligned.m8n8.x4.shared.b16 {%0,%1,%2,%3}, [%4];"
                 : "=r"(r[0]), "=r"(r[1]), "=r"(r[2]), "=r"(r[3]) : "r"(addr));
}
__device__ __forceinline__ unsigned h2u(__half2 h) {
    return *reinterpret_cast<unsigned*>(&h);
}

// ---------------- fused prep ----------------
#define N_CVTX (MROWS * KDIM / 4)
#define N_CVTW (QKV_N * KDIM / 4)
#define N_CVTP (DIM * KDIM / 4)
#define N_BIAS QKV_N
#define N_CPB  (TBL * NH)
#define N_TOT  (N_CVTX + N_CVTW + N_CVTP + N_BIAS + N_CPB)

__global__ void prep_fused(const float* __restrict__ x,
                           const float* __restrict__ qkv_w,
                           const float* __restrict__ proj_w,
                           const float* __restrict__ q_bias,
                           const float* __restrict__ v_bias,
                           const float* __restrict__ table,
                           const float* __restrict__ w1,
                           const float* __restrict__ b1,
                           const float* __restrict__ w2) {
    long long id = (long long)blockIdx.x * blockDim.x + threadIdx.x;
    if (id < N_CVTX) {
        float4 v = ((const float4*)x)[id];
        ((__half2*)g_xh)[2 * id]     = __floats2half2_rn(v.x, v.y);
        ((__half2*)g_xh)[2 * id + 1] = __floats2half2_rn(v.z, v.w);
        return;
    }
    id -= N_CVTX;
    if (id < N_CVTW) {
        float4 v = ((const float4*)qkv_w)[id];
        ((__half2*)g_wh)[2 * id]     = __floats2half2_rn(v.x, v.y);
        ((__half2*)g_wh)[2 * id + 1] = __floats2half2_rn(v.z, v.w);
        return;
    }
    id -= N_CVTW;
    if (id < N_CVTP) {
        float4 v = ((const float4*)proj_w)[id];
        ((__half2*)g_pwh)[2 * id]     = __floats2half2_rn(v.x, v.y);
        ((__half2*)g_pwh)[2 * id + 1] = __floats2half2_rn(v.z, v.w);
        return;
    }
    id -= N_CVTP;
    if (id < N_BIAS) {
        int n = (int)id;
        float b;
        if (n < DIM)          b = q_bias[n];
        else if (n < 2 * DIM) b = 0.0f;
        else                  b = v_bias[n - 2 * DIM];
        g_qkv_bias[n] = b;
        return;
    }
    id -= N_BIAS;
    if (id < N_CPB) {
        int t = (int)id / NH;
        int h = (int)id % NH;
        float c0 = table[t * 2 + 0];
        float c1 = table[t * 2 + 1];
        const float* w2h = w2 + h * CPBH;
        float acc = 0.0f;
        for (int j = 0; j < CPBH; j++) {
            float hid = fmaxf(c0 * w1[j * 2 + 0] + c1 * w1[j * 2 + 1] + b1[j], 0.0f);
            acc += hid * w2h[j];
        }
        g_bias_table[t * NH + h] = 16.0f / (1.0f + expf(-acc));
    }
}

// ---------------- bmF build: fragment-layout bias+mask ----------------
#define BMF_THREADS (NWMASK * NH * 4 * 7 * 32)   // 688128

__global__ void bmf_build(const float* __restrict__ mask,
                          const int* __restrict__ rel_idx) {
    int e = blockIdx.x * 256 + threadIdx.x;
    if (e >= BMF_THREADS) return;
    int lane = e & 31;
    int rest = e >> 5;
    int t  = rest % 7;  rest /= 7;
    int mi = rest & 3;  rest >>= 2;
    int h  = rest % NH;
    int w  = rest / NH;
    int r  = lane >> 2, cc = lane & 3;
    int i0 = mi * 16 + r, i1 = i0 + 8;
    int j0 = t * 8 + 2 * cc, j1 = j0 + 1;
    const float* mw = mask + (size_t)w * NN;
    float4 o;
    o.x = (i0 < NTOK && j0 < NTOK) ? g_bias_table[rel_idx[i0 * NTOK + j0] * NH + h] + mw[i0 * NTOK + j0] : -1e30f;
    o.y = (i0 < NTOK && j1 < NTOK) ? g_bias_table[rel_idx[i0 * NTOK + j1] * NH + h] + mw[i0 * NTOK + j1] : -1e30f;
    o.z = (i1 < NTOK && j0 < NTOK) ? g_bias_table[rel_idx[i1 * NTOK + j0] * NH + h] + mw[i1 * NTOK + j0] : -1e30f;
    o.w = (i1 < NTOK && j1 < NTOK) ? g_bias_table[rel_idx[i1 * NTOK + j1] * NH + h] + mw[i1 * NTOK + j1] : -1e30f;
    *(float4*)(g_bmF + (size_t)e * 4) = o;
}

// ---------------- fp16 mma.sync GEMM, cp.async 3-stage (unchanged from R7) ----------
#define LDH     40
#define A_ST    (256 * LDH)
#define B_ST    (128 * LDH)
#define STAGE_H (A_ST + B_ST)
#define GSMEM   (3 * STAGE_H * 2)

__global__ void __launch_bounds__(256, 1)
gemm_h2(const __half* __restrict__ A, const __half* __restrict__ W,
        const float* __restrict__ bias, float* __restrict__ C, int Ntot) {
    extern __shared__ __half smh[];
    const uint32_t sbase = smem_u32(smh);
    const int tid  = threadIdx.x;
    const int lane = tid & 31;
    const int wid  = tid >> 5;
    const int warpM = (wid >> 1) * 64;
    const int warpN = (wid & 1) * 64;
    const int bm = blockIdx.y * 256;
    const int bn = blockIdx.x * 128;

    const int sr = tid >> 2;
    const int un = tid & 3;
    const __half* Ag = A + (size_t)(bm + sr) * KDIM + un * 8;
    const __half* Wg = W + (size_t)(bn + sr) * KDIM + un * 8;
    const uint32_t stgOff = (uint32_t)(sr * LDH + un * 8) * 2;

    float c[4][8][4];
#pragma unroll
    for (int mi = 0; mi < 4; mi++)
#pragma unroll
        for (int ni = 0; ni < 8; ni++)
#pragma unroll
            for (int e = 0; e < 4; e++) c[mi][ni][e] = 0.0f;

    const int aRow = (lane & 7) + ((lane >> 3) & 1) * 8;
    const int aCol = ((lane >> 4) & 1) * 8;
    const int bRow = (lane & 7) + ((lane >> 4) & 1) * 8;
    const int bCol = ((lane >> 3) & 1) * 8;
    const uint32_t aFrag = sbase + (uint32_t)((warpM + aRow) * LDH + aCol) * 2;
    const uint32_t bFrag = sbase + (uint32_t)(A_ST + (warpN + bRow) * LDH + bCol) * 2;

#define ISSUE(stg, ch) do { \
    uint32_t _b = sbase + (stg) * (STAGE_H * 2) + stgOff; \
    const __half* _a = Ag + (ch) * 32; \
    cp16(_b,                  _a); \
    cp16(_b + 64 * LDH * 2,   _a + (size_t)64 * KDIM); \
    cp16(_b + 128 * LDH * 2,  _a + (size_t)128 * KDIM); \
    cp16(_b + 192 * LDH * 2,  _a + (size_t)192 * KDIM); \
    const __half* _w = Wg + (ch) * 32; \
    uint32_t _bb = _b + A_ST * 2; \
    cp16(_bb,                 _w); \
    cp16(_bb + 64 * LDH * 2,  _w + (size_t)64 * KDIM); \
} while (0)

    ISSUE(0, 0); CP_COMMIT();
    ISSUE(1, 1); CP_COMMIT();

#pragma unroll
    for (int ch = 0; ch < 12; ch++) {
        const int stg = ch % 3;
        CP_WAIT1();
        __syncthreads();
        if (ch + 2 < 12) { ISSUE((ch + 2) % 3, ch + 2); }
        CP_COMMIT();

        const uint32_t aB = aFrag + stg * (STAGE_H * 2);
        const uint32_t bB = bFrag + stg * (STAGE_H * 2);
#pragma unroll
        for (int s2 = 0; s2 < 2; s2++) {
            unsigned af[4][4], bf[4][4];
#pragma unroll
            for (int mi = 0; mi < 4; mi++)
                ldsm_x4(af[mi], aB + mi * (16 * LDH * 2) + s2 * 32);
#pragma unroll
            for (int p = 0; p < 4; p++)
                ldsm_x4(bf[p], bB + p * (16 * LDH * 2) + s2 * 32);
#pragma unroll
            for (int mi = 0; mi < 4; mi++)
#pragma unroll
                for (int p = 0; p < 4; p++) {
                    mma_f16(c[mi][2 * p],     af[mi], bf[p][0], bf[p][1]);
                    mma_f16(c[mi][2 * p + 1], af[mi], bf[p][2], bf[p][3]);
                }
        }
    }
#undef ISSUE

    const int r  = lane >> 2;
    const int cc = lane & 3;
#pragma unroll
    for (int mi = 0; mi < 4; mi++) {
        int row0 = bm + warpM + mi * 16 + r;
#pragma unroll
        for (int ni = 0; ni < 8; ni++) {
            int col = bn + warpN + ni * 8 + cc * 2;
            float2 b2 = *(const float2*)(bias + col);
            *(float2*)(C + (size_t)row0 * Ntot + col) =
                make_float2(c[mi][ni][0] + b2.x, c[mi][ni][1] + b2.y);
            *(float2*)(C + (size_t)(row0 + 8) * Ntot + col) =
                make_float2(c[mi][ni][2] + b2.x, c[mi][ni][3] + b2.y);
        }
    }
}

// ---------------- tensor-core attention: one warp per (b,h) ----------------
// smem: qh/qr/kh/kr [64][40] halfs, vT h/r [32][72] halfs
#define QK_LD 40
#define VT_LD 72

__global__ void __launch_bounds__(32)
attn6(const float* __restrict__ logit_scale) {
    const int bh = blockIdx.x;
    const int b = bh / NH;
    const int h = bh - b * NH;
    const int lane = threadIdx.x;

    __shared__ __align__(16) __half qh[64 * QK_LD];
    __shared__ __align__(16) __half qr[64 * QK_LD];
    __shared__ __align__(16) __half kh[64 * QK_LD];
    __shared__ __align__(16) __half kr[64 * QK_LD];
    __shared__ __align__(16) __half vh[HD * VT_LD];
    __shared__ __align__(16) __half vr[HD * VT_LD];

    // ---- zero pads ----
    for (int e = lane; e < (64 - NTOK) * QK_LD / 2; e += 32) {
        ((unsigned*)(qh + NTOK * QK_LD))[e] = 0;
        ((unsigned*)(qr + NTOK * QK_LD))[e] = 0;
        ((unsigned*)(kh + NTOK * QK_LD))[e] = 0;
        ((unsigned*)(kr + NTOK * QK_LD))[e] = 0;
    }
    for (int e = lane; e < HD * 12; e += 32) {     // cols 48..71 of vT rows
        int rowd = e / 12, cu = e % 12;
        ((unsigned*)(vh + rowd * VT_LD + 48))[cu] = 0;
        ((unsigned*)(vr + rowd * VT_LD + 48))[cu] = 0;
    }
    __syncwarp();

    const float scale = __expf(fminf(__ldg(logit_scale + h), 4.605170185988091f));
    const float* base = g_qkv + (size_t)b * NTOK * QKV_N + h * HD;

    // ---- fill q (scaled/normalized) and k (normalized), split h+r ----
    for (int t = lane; t < 2 * NTOK; t += 32) {
        int isK = t >= NTOK;
        int row = isK ? t - NTOK : t;
        const float* src = base + (size_t)row * QKV_N + (isK ? DIM : 0);
        float4 xs[8];
#pragma unroll
        for (int p = 0; p < 8; p++) xs[p] = *(const float4*)(src + p * 4);
        float sq = 0.0f;
#pragma unroll
        for (int p = 0; p < 8; p++)
            sq += xs[p].x * xs[p].x + xs[p].y * xs[p].y + xs[p].z * xs[p].z + xs[p].w * xs[p].w;
        float fs = (isK ? 1.0f : scale) / fmaxf(sqrtf(sq), 1e-12f);
        __half2* dh = (__half2*)((isK ? kh : qh) + row * QK_LD);
        __half2* dr = (__half2*)((isK ? kr : qr) + row * QK_LD);
#pragma unroll
        for (int p = 0; p < 8; p++) {
            float f0 = xs[p].x * fs, f1 = xs[p].y * fs;
            float f2 = xs[p].z * fs, f3 = xs[p].w * fs;
            __half2 h0 = __floats2half2_rn(f0, f1);
            __half2 h1 = __floats2half2_rn(f2, f3);
            float2 b0 = __half22float2(h0);
            float2 b1 = __half22float2(h1);
            dh[2 * p]     = h0;
            dh[2 * p + 1] = h1;
            dr[2 * p]     = __floats2half2_rn(f0 - b0.x, f1 - b0.y);
            dr[2 * p + 1] = __floats2half2_rn(f2 - b1.x, f3 - b1.y);
        }
    }
    // ---- fill vT (transposed), split h+r ----
    {
        const float* vsrc = base + 2 * DIM;
        for (int e = lane; e < NTOK * 8; e += 32) {
            int row = e >> 3, d4 = (e & 7) * 4;
            float4 v = *(const float4*)(vsrc + (size_t)row * QKV_N + d4);
            float vals[4] = {v.x, v.y, v.z, v.w};
#pragma unroll
            for (int cdx = 0; cdx < 4; cdx++) {
                int d = d4 + cdx;
                __half hv = __float2half_rn(vals[cdx]);
                vh[d * VT_LD + row] = hv;
                vr[d * VT_LD + row] = __float2half_rn(vals[cdx] - __half2float(hv));
            }
        }
    }
    __syncwarp();

    // ---- fragment base addresses ----
    const int aRow = (lane & 7) + ((lane >> 3) & 1) * 8;
    const int aCol = ((lane >> 4) & 1) * 8;
    const int bRow = (lane & 7) + ((lane >> 4) & 1) * 8;
    const int bCol = ((lane >> 3) & 1) * 8;
    const uint32_t qhB = smem_u32(qh) + (uint32_t)(aRow * QK_LD + aCol) * 2;
    const uint32_t qrB = smem_u32(qr) + (uint32_t)(aRow * QK_LD + aCol) * 2;
    const uint32_t khB = smem_u32(kh) + (uint32_t)(bRow * QK_LD + bCol) * 2;
    const uint32_t krB = smem_u32(kr) + (uint32_t)(bRow * QK_LD + bCol) * 2;
    const uint32_t vhB = smem_u32(vh) + (uint32_t)(bRow * VT_LD + bCol) * 2;
    const uint32_t vrB = smem_u32(vr) + (uint32_t)(bRow * VT_LD + bCol) * 2;

    const int r  = lane >> 2;
    const int cc = lane & 3;
    const float* bmbase = g_bmF + ((size_t)(b & (NWMASK - 1)) * NH + h) * BMF_PER_WH;

#pragma unroll 1
    for (int mi = 0; mi < 4; mi++) {
        // prefetch bias+mask fragments (coalesced)
        float4 bm[7];
        {
            const float4* bmp = (const float4*)(bmbase + (size_t)mi * 7 * 128) + lane;
#pragma unroll
            for (int t = 0; t < 7; t++) bm[t] = bmp[t * 32];
        }
        // q fragments for this row block
        unsigned qfh[2][4], qfr[2][4];
#pragma unroll
        for (int kc = 0; kc < 2; kc++) {
            ldsm_x4(qfh[kc], qhB + (uint32_t)(mi * 16 * QK_LD + kc * 16) * 2);
            ldsm_x4(qfr[kc], qrB + (uint32_t)(mi * 16 * QK_LD + kc * 16) * 2);
        }
        // QK^T with compensation
        float c[7][4];
#pragma unroll
        for (int t = 0; t < 7; t++)
#pragma unroll
            for (int e = 0; e < 4; e++) c[t][e] = 0.0f;
#pragma unroll
        for (int tp = 0; tp < 4; tp++) {
#pragma unroll
            for (int kc = 0; kc < 2; kc++) {
                unsigned kk[4], rrf[4];
                ldsm_x4(kk,  khB + (uint32_t)(tp * 16 * QK_LD + kc * 16) * 2);
                ldsm_x4(rrf, krB + (uint32_t)(tp * 16 * QK_LD + kc * 16) * 2);
                mma_f16(c[2 * tp], qfh[kc], kk[0], kk[1]);
                mma_f16(c[2 * tp], qfr[kc], kk[0], kk[1]);
                mma_f16(c[2 * tp], qfh[kc], rrf[0], rrf[1]);
                if (2 * tp + 1 < 7) {
                    mma_f16(c[2 * tp + 1], qfh[kc], kk[2], kk[3]);
                    mma_f16(c[2 * tp + 1], qfr[kc], kk[2], kk[3]);
                    mma_f16(c[2 * tp + 1], qfh[kc], rrf[2], rrf[3]);
                }
            }
        }
        // + bias + mask (pads get -1e30)
#pragma unroll
        for (int t = 0; t < 7; t++) {
            c[t][0] += bm[t].x; c[t][1] += bm[t].y;
            c[t][2] += bm[t].z; c[t][3] += bm[t].w;
        }
        // softmax rows r (c0,c1) and r+8 (c2,c3)
        float mx0 = -1e30f, mx1 = -1e30f;
#pragma unroll
        for (int t = 0; t < 7; t++) {
            mx0 = fmaxf(mx0, fmaxf(c[t][0], c[t][1]));
            mx1 = fmaxf(mx1, fmaxf(c[t][2], c[t][3]));
        }
        mx0 = fmaxf(mx0, __shfl_xor_sync(0xffffffffu, mx0, 1));
        mx0 = fmaxf(mx0, __shfl_xor_sync(0xffffffffu, mx0, 2));
        mx1 = fmaxf(mx1, __shfl_xor_sync(0xffffffffu, mx1, 1));
        mx1 = fmaxf(mx1, __shfl_xor_sync(0xffffffffu, mx1, 2));

        unsigned ph[7], phb[7], pr[7], prb[7];
        float s0 = 0.0f, s1 = 0.0f;
#pragma unroll
        for (int t = 0; t < 7; t++) {
            float p0 = __expf(c[t][0] - mx0);
            float p1 = __expf(c[t][1] - mx0);
            float p2 = __expf(c[t][2] - mx1);
            float p3 = __expf(c[t][3] - mx1);
            s0 += p0 + p1; s1 += p2 + p3;
            __half2 h0 = __floats2half2_rn(p0, p1);
            __half2 h1 = __floats2half2_rn(p2, p3);
            float2 f0 = __half22float2(h0);
            float2 f1 = __half22float2(h1);
            ph[t]  = h2u(h0);
            phb[t] = h2u(h1);
            pr[t]  = h2u(__floats2half2_rn(p0 - f0.x, p1 - f0.y));
            prb[t] = h2u(__floats2half2_rn(p2 - f1.x, p3 - f1.y));
        }
        s0 += __shfl_xor_sync(0xffffffffu, s0, 1);
        s0 += __shfl_xor_sync(0xffffffffu, s0, 2);
        s1 += __shfl_xor_sync(0xffffffffu, s1, 1);
        s1 += __shfl_xor_sync(0xffffffffu, s1, 2);

        // P @ V with compensation
        float o[4][4];
#pragma unroll
        for (int nt = 0; nt < 4; nt++)
#pragma unroll
            for (int e = 0; e < 4; e++) o[nt][e] = 0.0f;
#pragma unroll
        for (int s = 0; s < 4; s++) {
            unsigned ah[4] = { ph[2 * s], phb[2 * s],
                               (s < 3) ? ph[2 * s + 1] : 0u,
                               (s < 3) ? phb[2 * s + 1] : 0u };
            unsigned ar[4] = { pr[2 * s], prb[2 * s],
                               (s < 3) ? pr[2 * s + 1] : 0u,
                               (s < 3) ? prb[2 * s + 1] : 0u };
#pragma unroll
            for (int dp = 0; dp < 2; dp++) {
                unsigned vv[4], vw[4];
                ldsm_x4(vv, vhB + (uint32_t)(dp * 16 * VT_LD + s * 16) * 2);
                ldsm_x4(vw, vrB + (uint32_t)(dp * 16 * VT_LD + s * 16) * 2);
                mma_f16(o[2 * dp],     ah, vv[0], vv[1]);
                mma_f16(o[2 * dp],     ar, vv[0], vv[1]);
                mma_f16(o[2 * dp],     ah, vw[0], vw[1]);
                mma_f16(o[2 * dp + 1], ah, vv[2], vv[3]);
                mma_f16(o[2 * dp + 1], ar, vv[2], vv[3]);
                mma_f16(o[2 * dp + 1], ah, vw[2], vw[3]);
            }
        }
        // store (1/sum folded)
        float inv0 = 1.0f / s0;
        float inv1 = 1.0f / s1;
        int i0 = mi * 16 + r;
        if (i0 < NTOK) {
            __half* dst = g_atth + ((size_t)b * NTOK + i0) * DIM + h * HD + 2 * cc;
#pragma unroll
            for (int nt = 0; nt < 4; nt++)
                *(__half2*)(dst + nt * 8) = __floats2half2_rn(o[nt][0] * inv0, o[nt][1] * inv0);
        }
        int i1 = i0 + 8;
        if (i1 < NTOK) {
            __half* dst = g_atth + ((size_t)b * NTOK + i1) * DIM + h * HD + 2 * cc;
#pragma unroll
            for (int nt = 0; nt < 4; nt++)
                *(__half2*)(dst + nt * 8) = __floats2half2_rn(o[nt][2] * inv1, o[nt][3] * inv1);
        }
    }
}

// ---------------- launch ----------------
extern "C" void kernel_launch(void* const* d_in, const int* in_sizes, int n_in,
                              void* d_out, int out_size) {
    const float* x           = (const float*)d_in[0];
    const float* mask        = (const float*)d_in[1];
    const float* qkv_w       = (const float*)d_in[2];
    const float* q_bias      = (const float*)d_in[3];
    const float* v_bias      = (const float*)d_in[4];
    const float* logit_scale = (const float*)d_in[5];
    const float* cpb_w1      = (const float*)d_in[6];
    const float* cpb_b1      = (const float*)d_in[7];
    const float* cpb_w2      = (const float*)d_in[8];
    const float* proj_w      = (const float*)d_in[9];
    const float* proj_b      = (const float*)d_in[10];
    const float* rel_table   = (const float*)d_in[11];
    const int*   rel_idx     = (const int*)d_in[12];
    float* out = (float*)d_out;

    float*  qkv_scratch;  cudaGetSymbolAddress((void**)&qkv_scratch, g_qkv);
    __half* xh;           cudaGetSymbolAddress((void**)&xh, g_xh);
    __half* atth;         cudaGetSymbolAddress((void**)&atth, g_atth);
    __half* wh;           cudaGetSymbolAddress((void**)&wh, g_wh);
    __half* pwh;          cudaGetSymbolAddress((void**)&pwh, g_pwh);
    float*  qkv_bias_ptr; cudaGetSymbolAddress((void**)&qkv_bias_ptr, g_qkv_bias);

    cudaFuncSetAttribute(gemm_h2, cudaFuncAttributeMaxDynamicSharedMemorySize, GSMEM);

    // launch 0: fused prep
    prep_fused<<<(N_TOT + 255) / 256, 256>>>(x, qkv_w, proj_w, q_bias, v_bias,
                                             rel_table, cpb_w1, cpb_b1, cpb_w2);
    // launch 1: fragment-layout bias+mask
    bmf_build<<<(BMF_THREADS + 255) / 256, 256>>>(mask, rel_idx);

    // launch 2: QKV GEMM
    {
        dim3 grid(QKV_N / 128, MROWS / 256);
        gemm_h2<<<grid, 256, GSMEM>>>(xh, wh, qkv_bias_ptr, qkv_scratch, QKV_N);
    }

    // launch 3 (ncu profile slot): tensor-core attention
    attn6<<<B_WIN * NH, 32>>>(logit_scale);

    // launch 4: proj GEMM
    {
        dim3 grid(DIM / 128, MROWS / 256);
        gemm_h2<<<grid, 256, GSMEM>>>(atth, pwh, proj_b, out, DIM);
    }
}

// round 10
// speedup vs baseline: 5.0956x; 1.2478x over previous
#include <cuda_runtime.h>
#include <cuda_fp16.h>
#include <math.h>
#include <stdint.h>

// ---------------- problem constants ----------------
#define B_WIN   2048
#define NTOK    49
#define DIM     384
#define NH      12
#define HD      32
#define NWMASK  64
#define TBL     169
#define CPBH    512
#define QKV_N   1152
#define MROWS   (B_WIN * NTOK)    // 100352
#define NN      (NTOK * NTOK)     // 2401
#define KDIM    384

// ---------------- scratch (device globals) ----------------
__device__ float  g_qkv[(size_t)MROWS * QKV_N];
__device__ __half g_xh[(size_t)MROWS * KDIM];
__device__ __half g_atth[(size_t)MROWS * DIM];
__device__ __half g_wh[(size_t)QKV_N * KDIM];
__device__ __half g_pwh[(size_t)DIM * KDIM];
__device__ float  g_bias_table[TBL * NH];
__device__ float  g_qkv_bias[QKV_N];
// bias+mask in mma C-fragment layout: [w][h][mi(4)][t(7)][lane(32)][4]
#define BMF_PER_WH (4 * 7 * 128)
__device__ float  g_bmF[(size_t)NWMASK * NH * BMF_PER_WH];

// ---------------- helpers ----------------
__device__ __forceinline__ uint32_t smem_u32(const void* p) {
    uint32_t a;
    asm("{ .reg .u64 t; cvta.to.shared.u64 t, %1; cvt.u32.u64 %0, t; }" : "=r"(a) : "l"(p));
    return a;
}
__device__ __forceinline__ void cp16(uint32_t dst, const void* src) {
    asm volatile("cp.async.ca.shared.global [%0], [%1], 16;" :: "r"(dst), "l"(src));
}
#define CP_COMMIT() asm volatile("cp.async.commit_group;" ::: "memory")
#define CP_WAIT1()  asm volatile("cp.async.wait_group 1;" ::: "memory")

__device__ __forceinline__ void mma_f16(float* c, const unsigned* a,
                                        unsigned b0, unsigned b1) {
    asm volatile(
        "mma.sync.aligned.m16n8k16.row.col.f32.f16.f16.f32 "
        "{%0,%1,%2,%3}, {%4,%5,%6,%7}, {%8,%9}, {%0,%1,%2,%3};"
        : "+f"(c[0]), "+f"(c[1]), "+f"(c[2]), "+f"(c[3])
        : "r"(a[0]), "r"(a[1]), "r"(a[2]), "r"(a[3]), "r"(b0), "r"(b1));
}
__device__ __forceinline__ void ldsm_x4(unsigned* r, uint32_t addr) {
    asm volatile("ldmatrix.sync.aligned.m8n8.x4.shared.b16 {%0,%1,%2,%3}, [%4];"
                 : "=r"(r[0]), "=r"(r[1]), "=r"(r[2]), "=r"(r[3]) : "r"(addr));
}
__device__ __forceinline__ unsigned h2u(__half2 h) {
    return *reinterpret_cast<unsigned*>(&h);
}

// ---------------- fused prep ----------------
#define N_CVTX (MROWS * KDIM / 4)
#define N_CVTW (QKV_N * KDIM / 4)
#define N_CVTP (DIM * KDIM / 4)
#define N_BIAS QKV_N
#define N_CPB  (TBL * NH)
#define N_TOT  (N_CVTX + N_CVTW + N_CVTP + N_BIAS + N_CPB)

__global__ void prep_fused(const float* __restrict__ x,
                           const float* __restrict__ qkv_w,
                           const float* __restrict__ proj_w,
                           const float* __restrict__ q_bias,
                           const float* __restrict__ v_bias,
                           const float* __restrict__ table,
                           const float* __restrict__ w1,
                           const float* __restrict__ b1,
                           const float* __restrict__ w2) {
    long long id = (long long)blockIdx.x * blockDim.x + threadIdx.x;
    if (id < N_CVTX) {
        float4 v = ((const float4*)x)[id];
        ((__half2*)g_xh)[2 * id]     = __floats2half2_rn(v.x, v.y);
        ((__half2*)g_xh)[2 * id + 1] = __floats2half2_rn(v.z, v.w);
        return;
    }
    id -= N_CVTX;
    if (id < N_CVTW) {
        float4 v = ((const float4*)qkv_w)[id];
        ((__half2*)g_wh)[2 * id]     = __floats2half2_rn(v.x, v.y);
        ((__half2*)g_wh)[2 * id + 1] = __floats2half2_rn(v.z, v.w);
        return;
    }
    id -= N_CVTW;
    if (id < N_CVTP) {
        float4 v = ((const float4*)proj_w)[id];
        ((__half2*)g_pwh)[2 * id]     = __floats2half2_rn(v.x, v.y);
        ((__half2*)g_pwh)[2 * id + 1] = __floats2half2_rn(v.z, v.w);
        return;
    }
    id -= N_CVTP;
    if (id < N_BIAS) {
        int n = (int)id;
        float b;
        if (n < DIM)          b = q_bias[n];
        else if (n < 2 * DIM) b = 0.0f;
        else                  b = v_bias[n - 2 * DIM];
        g_qkv_bias[n] = b;
        return;
    }
    id -= N_BIAS;
    if (id < N_CPB) {
        int t = (int)id / NH;
        int h = (int)id % NH;
        float c0 = table[t * 2 + 0];
        float c1 = table[t * 2 + 1];
        const float* w2h = w2 + h * CPBH;
        float acc = 0.0f;
        for (int j = 0; j < CPBH; j++) {
            float hid = fmaxf(c0 * w1[j * 2 + 0] + c1 * w1[j * 2 + 1] + b1[j], 0.0f);
            acc += hid * w2h[j];
        }
        g_bias_table[t * NH + h] = 16.0f / (1.0f + expf(-acc));
    }
}

// ---------------- bmF build ----------------
#define BMF_THREADS (NWMASK * NH * 4 * 7 * 32)

__global__ void bmf_build(const float* __restrict__ mask,
                          const int* __restrict__ rel_idx) {
    int e = blockIdx.x * 256 + threadIdx.x;
    if (e >= BMF_THREADS) return;
    int lane = e & 31;
    int rest = e >> 5;
    int t  = rest % 7;  rest /= 7;
    int mi = rest & 3;  rest >>= 2;
    int h  = rest % NH;
    int w  = rest / NH;
    int r  = lane >> 2, cc = lane & 3;
    int i0 = mi * 16 + r, i1 = i0 + 8;
    int j0 = t * 8 + 2 * cc, j1 = j0 + 1;
    const float* mw = mask + (size_t)w * NN;
    float4 o;
    o.x = (i0 < NTOK && j0 < NTOK) ? g_bias_table[rel_idx[i0 * NTOK + j0] * NH + h] + mw[i0 * NTOK + j0] : -1e30f;
    o.y = (i0 < NTOK && j1 < NTOK) ? g_bias_table[rel_idx[i0 * NTOK + j1] * NH + h] + mw[i0 * NTOK + j1] : -1e30f;
    o.z = (i1 < NTOK && j0 < NTOK) ? g_bias_table[rel_idx[i1 * NTOK + j0] * NH + h] + mw[i1 * NTOK + j0] : -1e30f;
    o.w = (i1 < NTOK && j1 < NTOK) ? g_bias_table[rel_idx[i1 * NTOK + j1] * NH + h] + mw[i1 * NTOK + j1] : -1e30f;
    *(float4*)(g_bmF + (size_t)e * 4) = o;
}

// ---------------- fp16 mma.sync GEMM, cp.async 3-stage ----------------
#define LDH     40
#define A_ST    (256 * LDH)
#define B_ST    (128 * LDH)
#define STAGE_H (A_ST + B_ST)
#define GSMEM   (3 * STAGE_H * 2)

__global__ void __launch_bounds__(256, 1)
gemm_h2(const __half* __restrict__ A, const __half* __restrict__ W,
        const float* __restrict__ bias, float* __restrict__ C, int Ntot) {
    extern __shared__ __half smh[];
    const uint32_t sbase = smem_u32(smh);
    const int tid  = threadIdx.x;
    const int lane = tid & 31;
    const int wid  = tid >> 5;
    const int warpM = (wid >> 1) * 64;
    const int warpN = (wid & 1) * 64;
    const int bm = blockIdx.y * 256;
    const int bn = blockIdx.x * 128;

    const int sr = tid >> 2;
    const int un = tid & 3;
    const __half* Ag = A + (size_t)(bm + sr) * KDIM + un * 8;
    const __half* Wg = W + (size_t)(bn + sr) * KDIM + un * 8;
    const uint32_t stgOff = (uint32_t)(sr * LDH + un * 8) * 2;

    float c[4][8][4];
#pragma unroll
    for (int mi = 0; mi < 4; mi++)
#pragma unroll
        for (int ni = 0; ni < 8; ni++)
#pragma unroll
            for (int e = 0; e < 4; e++) c[mi][ni][e] = 0.0f;

    const int aRow = (lane & 7) + ((lane >> 3) & 1) * 8;
    const int aCol = ((lane >> 4) & 1) * 8;
    const int bRow = (lane & 7) + ((lane >> 4) & 1) * 8;
    const int bCol = ((lane >> 3) & 1) * 8;
    const uint32_t aFrag = sbase + (uint32_t)((warpM + aRow) * LDH + aCol) * 2;
    const uint32_t bFrag = sbase + (uint32_t)(A_ST + (warpN + bRow) * LDH + bCol) * 2;

#define ISSUE(stg, ch) do { \
    uint32_t _b = sbase + (stg) * (STAGE_H * 2) + stgOff; \
    const __half* _a = Ag + (ch) * 32; \
    cp16(_b,                  _a); \
    cp16(_b + 64 * LDH * 2,   _a + (size_t)64 * KDIM); \
    cp16(_b + 128 * LDH * 2,  _a + (size_t)128 * KDIM); \
    cp16(_b + 192 * LDH * 2,  _a + (size_t)192 * KDIM); \
    const __half* _w = Wg + (ch) * 32; \
    uint32_t _bb = _b + A_ST * 2; \
    cp16(_bb,                 _w); \
    cp16(_bb + 64 * LDH * 2,  _w + (size_t)64 * KDIM); \
} while (0)

    ISSUE(0, 0); CP_COMMIT();
    ISSUE(1, 1); CP_COMMIT();

#pragma unroll
    for (int ch = 0; ch < 12; ch++) {
        const int stg = ch % 3;
        CP_WAIT1();
        __syncthreads();
        if (ch + 2 < 12) { ISSUE((ch + 2) % 3, ch + 2); }
        CP_COMMIT();

        const uint32_t aB = aFrag + stg * (STAGE_H * 2);
        const uint32_t bB = bFrag + stg * (STAGE_H * 2);
#pragma unroll
        for (int s2 = 0; s2 < 2; s2++) {
            unsigned af[4][4], bf[4][4];
#pragma unroll
            for (int mi = 0; mi < 4; mi++)
                ldsm_x4(af[mi], aB + mi * (16 * LDH * 2) + s2 * 32);
#pragma unroll
            for (int p = 0; p < 4; p++)
                ldsm_x4(bf[p], bB + p * (16 * LDH * 2) + s2 * 32);
#pragma unroll
            for (int mi = 0; mi < 4; mi++)
#pragma unroll
                for (int p = 0; p < 4; p++) {
                    mma_f16(c[mi][2 * p],     af[mi], bf[p][0], bf[p][1]);
                    mma_f16(c[mi][2 * p + 1], af[mi], bf[p][2], bf[p][3]);
                }
        }
    }
#undef ISSUE

    const int r  = lane >> 2;
    const int cc = lane & 3;
#pragma unroll
    for (int mi = 0; mi < 4; mi++) {
        int row0 = bm + warpM + mi * 16 + r;
#pragma unroll
        for (int ni = 0; ni < 8; ni++) {
            int col = bn + warpN + ni * 8 + cc * 2;
            float2 b2 = *(const float2*)(bias + col);
            *(float2*)(C + (size_t)row0 * Ntot + col) =
                make_float2(c[mi][ni][0] + b2.x, c[mi][ni][1] + b2.y);
            *(float2*)(C + (size_t)(row0 + 8) * Ntot + col) =
                make_float2(c[mi][ni][2] + b2.x, c[mi][ni][3] + b2.y);
        }
    }
}

// ---------------- tensor-core attention: 4 warps per (b,h), warp = mi block ----
#define QK_LD 40
#define VT_LD 72

__global__ void __launch_bounds__(128)
attn7(const float* __restrict__ logit_scale) {
    const int bh = blockIdx.x;
    const int b = bh / NH;
    const int h = bh - b * NH;
    const int tid  = threadIdx.x;
    const int lane = tid & 31;
    const int mi   = tid >> 5;     // warp id = row-block

    __shared__ __align__(16) __half qh[64 * QK_LD];
    __shared__ __align__(16) __half qr[64 * QK_LD];
    __shared__ __align__(16) __half kh[64 * QK_LD];
    __shared__ __align__(16) __half kr[64 * QK_LD];
    __shared__ __align__(16) __half vh[HD * VT_LD];
    __shared__ __align__(16) __half vr[HD * VT_LD];

    // zero pads (q/k rows 49..63; vT cols 48..71)
    for (int e = tid; e < (64 - NTOK) * QK_LD / 2; e += 128) {
        ((unsigned*)(qh + NTOK * QK_LD))[e] = 0;
        ((unsigned*)(qr + NTOK * QK_LD))[e] = 0;
        ((unsigned*)(kh + NTOK * QK_LD))[e] = 0;
        ((unsigned*)(kr + NTOK * QK_LD))[e] = 0;
    }
    for (int e = tid; e < HD * 12; e += 128) {
        int rowd = e / 12, cu = e % 12;
        ((unsigned*)(vh + rowd * VT_LD + 48))[cu] = 0;
        ((unsigned*)(vr + rowd * VT_LD + 48))[cu] = 0;
    }

    const float scale = __expf(fminf(__ldg(logit_scale + h), 4.605170185988091f));
    const float* base = g_qkv + (size_t)b * NTOK * QKV_N + h * HD;

    // q (scaled/normalized) + k (normalized), split h+r — one row per thread
    for (int t = tid; t < 2 * NTOK; t += 128) {
        int isK = t >= NTOK;
        int row = isK ? t - NTOK : t;
        const float* src = base + (size_t)row * QKV_N + (isK ? DIM : 0);
        float4 xs[8];
#pragma unroll
        for (int p = 0; p < 8; p++) xs[p] = *(const float4*)(src + p * 4);
        float sq = 0.0f;
#pragma unroll
        for (int p = 0; p < 8; p++)
            sq += xs[p].x * xs[p].x + xs[p].y * xs[p].y + xs[p].z * xs[p].z + xs[p].w * xs[p].w;
        float fs = (isK ? 1.0f : scale) / fmaxf(sqrtf(sq), 1e-12f);
        __half2* dh = (__half2*)((isK ? kh : qh) + row * QK_LD);
        __half2* dr = (__half2*)((isK ? kr : qr) + row * QK_LD);
#pragma unroll
        for (int p = 0; p < 8; p++) {
            float f0 = xs[p].x * fs, f1 = xs[p].y * fs;
            float f2 = xs[p].z * fs, f3 = xs[p].w * fs;
            __half2 h0 = __floats2half2_rn(f0, f1);
            __half2 h1 = __floats2half2_rn(f2, f3);
            float2 b0 = __half22float2(h0);
            float2 b1 = __half22float2(h1);
            dh[2 * p]     = h0;
            dh[2 * p + 1] = h1;
            dr[2 * p]     = __floats2half2_rn(f0 - b0.x, f1 - b0.y);
            dr[2 * p + 1] = __floats2half2_rn(f2 - b1.x, f3 - b1.y);
        }
    }
    // vT (transposed), split h+r
    {
        const float* vsrc = base + 2 * DIM;
        for (int e = tid; e < NTOK * 8; e += 128) {
            int row = e >> 3, d4 = (e & 7) * 4;
            float4 v = *(const float4*)(vsrc + (size_t)row * QKV_N + d4);
            float vals[4] = {v.x, v.y, v.z, v.w};
#pragma unroll
            for (int cdx = 0; cdx < 4; cdx++) {
                int d = d4 + cdx;
                __half hv = __float2half_rn(vals[cdx]);
                vh[d * VT_LD + row] = hv;
                vr[d * VT_LD + row] = __float2half_rn(vals[cdx] - __half2float(hv));
            }
        }
    }
    __syncthreads();

    // fragment base addresses
    const int aRow = (lane & 7) + ((lane >> 3) & 1) * 8;
    const int aCol = ((lane >> 4) & 1) * 8;
    const int bRow = (lane & 7) + ((lane >> 4) & 1) * 8;
    const int bCol = ((lane >> 3) & 1) * 8;
    const uint32_t qhB = smem_u32(qh) + (uint32_t)(aRow * QK_LD + aCol) * 2;
    const uint32_t qrB = smem_u32(qr) + (uint32_t)(aRow * QK_LD + aCol) * 2;
    const uint32_t khB = smem_u32(kh) + (uint32_t)(bRow * QK_LD + bCol) * 2;
    const uint32_t krB = smem_u32(kr) + (uint32_t)(bRow * QK_LD + bCol) * 2;
    const uint32_t vhB = smem_u32(vh) + (uint32_t)(bRow * VT_LD + bCol) * 2;
    const uint32_t vrB = smem_u32(vr) + (uint32_t)(bRow * VT_LD + bCol) * 2;

    const int r  = lane >> 2;
    const int cc = lane & 3;
    const float* bmbase = g_bmF + ((size_t)(b & (NWMASK - 1)) * NH + h) * BMF_PER_WH;

    // ---- this warp's row block (mi) ----
    float4 bm[7];
    {
        const float4* bmp = (const float4*)(bmbase + (size_t)mi * 7 * 128) + lane;
#pragma unroll
        for (int t = 0; t < 7; t++) bm[t] = bmp[t * 32];
    }
    unsigned qfh[2][4], qfr[2][4];
#pragma unroll
    for (int kc = 0; kc < 2; kc++) {
        ldsm_x4(qfh[kc], qhB + (uint32_t)(mi * 16 * QK_LD + kc * 16) * 2);
        ldsm_x4(qfr[kc], qrB + (uint32_t)(mi * 16 * QK_LD + kc * 16) * 2);
    }
    float c[7][4];
#pragma unroll
    for (int t = 0; t < 7; t++)
#pragma unroll
        for (int e = 0; e < 4; e++) c[t][e] = 0.0f;
#pragma unroll
    for (int tp = 0; tp < 4; tp++) {
#pragma unroll
        for (int kc = 0; kc < 2; kc++) {
            unsigned kk[4], rrf[4];
            ldsm_x4(kk,  khB + (uint32_t)(tp * 16 * QK_LD + kc * 16) * 2);
            ldsm_x4(rrf, krB + (uint32_t)(tp * 16 * QK_LD + kc * 16) * 2);
            mma_f16(c[2 * tp], qfh[kc], kk[0], kk[1]);
            mma_f16(c[2 * tp], qfr[kc], kk[0], kk[1]);
            mma_f16(c[2 * tp], qfh[kc], rrf[0], rrf[1]);
            if (2 * tp + 1 < 7) {
                mma_f16(c[2 * tp + 1], qfh[kc], kk[2], kk[3]);
                mma_f16(c[2 * tp + 1], qfr[kc], kk[2], kk[3]);
                mma_f16(c[2 * tp + 1], qfh[kc], rrf[2], rrf[3]);
            }
        }
    }
#pragma unroll
    for (int t = 0; t < 7; t++) {
        c[t][0] += bm[t].x; c[t][1] += bm[t].y;
        c[t][2] += bm[t].z; c[t][3] += bm[t].w;
    }
    // softmax rows r (c0,c1) / r+8 (c2,c3)
    float mx0 = -1e30f, mx1 = -1e30f;
#pragma unroll
    for (int t = 0; t < 7; t++) {
        mx0 = fmaxf(mx0, fmaxf(c[t][0], c[t][1]));
        mx1 = fmaxf(mx1, fmaxf(c[t][2], c[t][3]));
    }
    mx0 = fmaxf(mx0, __shfl_xor_sync(0xffffffffu, mx0, 1));
    mx0 = fmaxf(mx0, __shfl_xor_sync(0xffffffffu, mx0, 2));
    mx1 = fmaxf(mx1, __shfl_xor_sync(0xffffffffu, mx1, 1));
    mx1 = fmaxf(mx1, __shfl_xor_sync(0xffffffffu, mx1, 2));

    unsigned ph[7], phb[7], pr[7], prb[7];
    float s0 = 0.0f, s1 = 0.0f;
#pragma unroll
    for (int t = 0; t < 7; t++) {
        float p0 = __expf(c[t][0] - mx0);
        float p1 = __expf(c[t][1] - mx0);
        float p2 = __expf(c[t][2] - mx1);
        float p3 = __expf(c[t][3] - mx1);
        s0 += p0 + p1; s1 += p2 + p3;
        __half2 h0 = __floats2half2_rn(p0, p1);
        __half2 h1 = __floats2half2_rn(p2, p3);
        float2 f0 = __half22float2(h0);
        float2 f1 = __half22float2(h1);
        ph[t]  = h2u(h0);
        phb[t] = h2u(h1);
        pr[t]  = h2u(__floats2half2_rn(p0 - f0.x, p1 - f0.y));
        prb[t] = h2u(__floats2half2_rn(p2 - f1.x, p3 - f1.y));
    }
    s0 += __shfl_xor_sync(0xffffffffu, s0, 1);
    s0 += __shfl_xor_sync(0xffffffffu, s0, 2);
    s1 += __shfl_xor_sync(0xffffffffu, s1, 1);
    s1 += __shfl_xor_sync(0xffffffffu, s1, 2);

    float o[4][4];
#pragma unroll
    for (int nt = 0; nt < 4; nt++)
#pragma unroll
        for (int e = 0; e < 4; e++) o[nt][e] = 0.0f;
#pragma unroll
    for (int s = 0; s < 4; s++) {
        unsigned ah[4] = { ph[2 * s], phb[2 * s],
                           (s < 3) ? ph[2 * s + 1] : 0u,
                           (s < 3) ? phb[2 * s + 1] : 0u };
        unsigned ar[4] = { pr[2 * s], prb[2 * s],
                           (s < 3) ? pr[2 * s + 1] : 0u,
                           (s < 3) ? prb[2 * s + 1] : 0u };
#pragma unroll
        for (int dp = 0; dp < 2; dp++) {
            unsigned vv[4], vw[4];
            ldsm_x4(vv, vhB + (uint32_t)(dp * 16 * VT_LD + s * 16) * 2);
            ldsm_x4(vw, vrB + (uint32_t)(dp * 16 * VT_LD + s * 16) * 2);
            mma_f16(o[2 * dp],     ah, vv[0], vv[1]);
            mma_f16(o[2 * dp],     ar, vv[0], vv[1]);
            mma_f16(o[2 * dp],     ah, vw[0], vw[1]);
            mma_f16(o[2 * dp + 1], ah, vv[2], vv[3]);
            mma_f16(o[2 * dp + 1], ar, vv[2], vv[3]);
            mma_f16(o[2 * dp + 1], ah, vw[2], vw[3]);
        }
    }
    float inv0 = 1.0f / s0;
    float inv1 = 1.0f / s1;
    int i0 = mi * 16 + r;
    if (i0 < NTOK) {
        __half* dst = g_atth + ((size_t)b * NTOK + i0) * DIM + h * HD + 2 * cc;
#pragma unroll
        for (int nt = 0; nt < 4; nt++)
            *(__half2*)(dst + nt * 8) = __floats2half2_rn(o[nt][0] * inv0, o[nt][1] * inv0);
    }
    int i1 = i0 + 8;
    if (i1 < NTOK) {
        __half* dst = g_atth + ((size_t)b * NTOK + i1) * DIM + h * HD + 2 * cc;
#pragma unroll
        for (int nt = 0; nt < 4; nt++)
            *(__half2*)(dst + nt * 8) = __floats2half2_rn(o[nt][2] * inv1, o[nt][3] * inv1);
    }
}

// ---------------- launch ----------------
extern "C" void kernel_launch(void* const* d_in, const int* in_sizes, int n_in,
                              void* d_out, int out_size) {
    const float* x           = (const float*)d_in[0];
    const float* mask        = (const float*)d_in[1];
    const float* qkv_w       = (const float*)d_in[2];
    const float* q_bias      = (const float*)d_in[3];
    const float* v_bias      = (const float*)d_in[4];
    const float* logit_scale = (const float*)d_in[5];
    const float* cpb_w1      = (const float*)d_in[6];
    const float* cpb_b1      = (const float*)d_in[7];
    const float* cpb_w2      = (const float*)d_in[8];
    const float* proj_w      = (const float*)d_in[9];
    const float* proj_b      = (const float*)d_in[10];
    const float* rel_table   = (const float*)d_in[11];
    const int*   rel_idx     = (const int*)d_in[12];
    float* out = (float*)d_out;

    float*  qkv_scratch;  cudaGetSymbolAddress((void**)&qkv_scratch, g_qkv);
    __half* xh;           cudaGetSymbolAddress((void**)&xh, g_xh);
    __half* atth;         cudaGetSymbolAddress((void**)&atth, g_atth);
    __half* wh;           cudaGetSymbolAddress((void**)&wh, g_wh);
    __half* pwh;          cudaGetSymbolAddress((void**)&pwh, g_pwh);
    float*  qkv_bias_ptr; cudaGetSymbolAddress((void**)&qkv_bias_ptr, g_qkv_bias);

    cudaFuncSetAttribute(gemm_h2, cudaFuncAttributeMaxDynamicSharedMemorySize, GSMEM);

    // launch 0: fused prep
    prep_fused<<<(N_TOT + 255) / 256, 256>>>(x, qkv_w, proj_w, q_bias, v_bias,
                                             rel_table, cpb_w1, cpb_b1, cpb_w2);
    // launch 1: fragment-layout bias+mask
    bmf_build<<<(BMF_THREADS + 255) / 256, 256>>>(mask, rel_idx);

    // launch 2: QKV GEMM
    {
        dim3 grid(QKV_N / 128, MROWS / 256);
        gemm_h2<<<grid, 256, GSMEM>>>(xh, wh, qkv_bias_ptr, qkv_scratch, QKV_N);
    }

    // launch 3 (ncu profile slot): tensor-core attention, 4 warps/(b,h)
    attn7<<<B_WIN * NH, 128>>>(logit_scale);

    // launch 4: proj GEMM
    {
        dim3 grid(DIM / 128, MROWS / 256);
        gemm_h2<<<grid, 256, GSMEM>>>(atth, pwh, proj_b, out, DIM);
    }
}